// round 1
// baseline (speedup 1.0000x reference)
#include <cuda_runtime.h>
#include <math.h>

// ---------------------------------------------------------------------------
// CrossAttention: B=8, T=S=2048, D=1024 (single head, d_k = 1024)
//   Q = target @ Wq^T + bq ; K = source @ Wk^T + bk ; V = source @ Wv^T + bv
//   S = softmax(Q K^T / 32) ; ctx = S V ; out = ctx @ Wo^T + bo
// Round-0 baseline: fp32 tiled SGEMMs (128x128x16, 8x8 microtile) + row softmax.
// ---------------------------------------------------------------------------

#define EMBED 1024
#define BATCH 8
#define SEQ   2048

// Scratch (device globals: allocation-free per harness rules)
__device__ float g_Q[BATCH * SEQ * EMBED];     // 64 MB
__device__ float g_K[BATCH * SEQ * EMBED];     // 64 MB
__device__ float g_V[BATCH * SEQ * EMBED];     // 64 MB
__device__ float g_S[(long long)BATCH * SEQ * SEQ]; // 134 MB
__device__ float g_C[BATCH * SEQ * EMBED];     // 64 MB

#define BM 128
#define BN 128
#define BK 16
// 256 threads, each computes 8x8 (split 4+4 in each dim for conflict-free LDS)

template <bool BT, bool HAS_BIAS>
__global__ __launch_bounds__(256)
void sgemm_kernel(const float* __restrict__ A,
                  const float* __restrict__ B,
                  const float* __restrict__ bias,
                  float* __restrict__ C,
                  int M, int N, int K,
                  long long sA, long long sB, long long sC,
                  float alpha)
{
    A += (long long)blockIdx.z * sA;
    B += (long long)blockIdx.z * sB;
    C += (long long)blockIdx.z * sC;

    __shared__ float As[BK][BM + 4];
    __shared__ float Bs[BK][BN + 4];

    const int tid = threadIdx.x;
    const int tx  = tid & 15;   // N direction
    const int ty  = tid >> 4;   // M direction

    const int m0 = blockIdx.y * BM;
    const int n0 = blockIdx.x * BN;

    float acc[8][8];
#pragma unroll
    for (int i = 0; i < 8; i++)
#pragma unroll
        for (int j = 0; j < 8; j++) acc[i][j] = 0.0f;

    const int nK = K / BK;
    for (int kt = 0; kt < nK; kt++) {
        const int k0 = kt * BK;

        // ---- load A tile: BM x BK (A row-major M x K), store transposed ----
#pragma unroll
        for (int it = 0; it < 2; it++) {
            int idx  = tid + it * 256;          // 0..511
            int row  = idx >> 2;                // 0..127
            int col4 = idx & 3;                 // 0..3
            float4 v = *(const float4*)&A[(long long)(m0 + row) * K + k0 + col4 * 4];
            As[col4 * 4 + 0][row] = v.x;
            As[col4 * 4 + 1][row] = v.y;
            As[col4 * 4 + 2][row] = v.z;
            As[col4 * 4 + 3][row] = v.w;
        }

        // ---- load B tile ----
        if (BT) {
            // B is N x K row-major (weights / K^T): BN rows of BK
#pragma unroll
            for (int it = 0; it < 2; it++) {
                int idx  = tid + it * 256;
                int row  = idx >> 2;            // n within tile
                int col4 = idx & 3;             // k/4
                float4 v = *(const float4*)&B[(long long)(n0 + row) * K + k0 + col4 * 4];
                Bs[col4 * 4 + 0][row] = v.x;
                Bs[col4 * 4 + 1][row] = v.y;
                Bs[col4 * 4 + 2][row] = v.z;
                Bs[col4 * 4 + 3][row] = v.w;
            }
        } else {
            // B is K x N row-major (V in attn@V): BK rows of BN
#pragma unroll
            for (int it = 0; it < 2; it++) {
                int idx  = tid + it * 256;
                int row  = idx >> 5;            // k within tile (0..15)
                int col4 = idx & 31;            // n/4
                float4 v = *(const float4*)&B[(long long)(k0 + row) * N + n0 + col4 * 4];
                *(float4*)&Bs[row][col4 * 4] = v;
            }
        }
        __syncthreads();

        // ---- compute ----
#pragma unroll
        for (int k = 0; k < BK; k++) {
            float a[8], b[8];
            *(float4*)&a[0] = *(const float4*)&As[k][ty * 4];
            *(float4*)&a[4] = *(const float4*)&As[k][64 + ty * 4];
            *(float4*)&b[0] = *(const float4*)&Bs[k][tx * 4];
            *(float4*)&b[4] = *(const float4*)&Bs[k][64 + tx * 4];
#pragma unroll
            for (int i = 0; i < 8; i++)
#pragma unroll
                for (int j = 0; j < 8; j++)
                    acc[i][j] = fmaf(a[i], b[j], acc[i][j]);
        }
        __syncthreads();
    }

    // ---- epilogue ----
#pragma unroll
    for (int ii = 0; ii < 2; ii++) {
#pragma unroll
        for (int i = 0; i < 4; i++) {
            int r = m0 + ii * 64 + ty * 4 + i;
#pragma unroll
            for (int jj = 0; jj < 2; jj++) {
                int c = n0 + jj * 64 + tx * 4;
                float4 v;
                v.x = alpha * acc[ii * 4 + i][jj * 4 + 0];
                v.y = alpha * acc[ii * 4 + i][jj * 4 + 1];
                v.z = alpha * acc[ii * 4 + i][jj * 4 + 2];
                v.w = alpha * acc[ii * 4 + i][jj * 4 + 3];
                if (HAS_BIAS) {
                    float4 bv = *(const float4*)&bias[c];
                    v.x += bv.x; v.y += bv.y; v.z += bv.z; v.w += bv.w;
                }
                *(float4*)&C[(long long)r * N + c] = v;
            }
        }
    }
}

// ---------------------------------------------------------------------------
// Row softmax over 2048 columns, one block (256 threads) per row, in place.
// ---------------------------------------------------------------------------
__global__ __launch_bounds__(256)
void softmax_kernel(float* __restrict__ S)
{
    float* row = S + (long long)blockIdx.x * SEQ;
    const int t = threadIdx.x;
    const int lane = t & 31;
    const int wid  = t >> 5;

    float4 v0 = ((const float4*)row)[t];
    float4 v1 = ((const float4*)row)[t + 256];

    float m = fmaxf(fmaxf(fmaxf(v0.x, v0.y), fmaxf(v0.z, v0.w)),
                    fmaxf(fmaxf(v1.x, v1.y), fmaxf(v1.z, v1.w)));
#pragma unroll
    for (int o = 16; o > 0; o >>= 1)
        m = fmaxf(m, __shfl_xor_sync(0xFFFFFFFFu, m, o));

    __shared__ float red[8];
    if (lane == 0) red[wid] = m;
    __syncthreads();
    float M = red[0];
#pragma unroll
    for (int i = 1; i < 8; i++) M = fmaxf(M, red[i]);
    __syncthreads();

    v0.x = __expf(v0.x - M); v0.y = __expf(v0.y - M);
    v0.z = __expf(v0.z - M); v0.w = __expf(v0.w - M);
    v1.x = __expf(v1.x - M); v1.y = __expf(v1.y - M);
    v1.z = __expf(v1.z - M); v1.w = __expf(v1.w - M);

    float s = (v0.x + v0.y + v0.z + v0.w) + (v1.x + v1.y + v1.z + v1.w);
#pragma unroll
    for (int o = 16; o > 0; o >>= 1)
        s += __shfl_xor_sync(0xFFFFFFFFu, s, o);
    if (lane == 0) red[wid] = s;
    __syncthreads();
    float Ssum = 0.0f;
#pragma unroll
    for (int i = 0; i < 8; i++) Ssum += red[i];

    float inv = 1.0f / Ssum;
    v0.x *= inv; v0.y *= inv; v0.z *= inv; v0.w *= inv;
    v1.x *= inv; v1.y *= inv; v1.z *= inv; v1.w *= inv;

    ((float4*)row)[t]       = v0;
    ((float4*)row)[t + 256] = v1;
}

extern "C" void kernel_launch(void* const* d_in, const int* in_sizes, int n_in,
                              void* d_out, int out_size)
{
    const float* target = (const float*)d_in[0];
    const float* source = (const float*)d_in[1];
    const float* Wq     = (const float*)d_in[2];
    const float* bq     = (const float*)d_in[3];
    const float* Wk     = (const float*)d_in[4];
    const float* bk     = (const float*)d_in[5];
    const float* Wv     = (const float*)d_in[6];
    const float* bv     = (const float*)d_in[7];
    const float* Wo     = (const float*)d_in[8];
    const float* bo     = (const float*)d_in[9];
    float* out = (float*)d_out;

    float *Q, *K, *V, *S, *C;
    cudaGetSymbolAddress((void**)&Q, g_Q);
    cudaGetSymbolAddress((void**)&K, g_K);
    cudaGetSymbolAddress((void**)&V, g_V);
    cudaGetSymbolAddress((void**)&S, g_S);
    cudaGetSymbolAddress((void**)&C, g_C);

    const int M  = BATCH * SEQ;   // 16384
    const int D  = EMBED;         // 1024

    // Projections: [16384,1024] = X @ W^T + b
    dim3 gProj(D / BN, M / BM, 1);
    sgemm_kernel<true, true><<<gProj, 256>>>(target, Wq, bq, Q, M, D, D, 0, 0, 0, 1.0f);
    sgemm_kernel<true, true><<<gProj, 256>>>(source, Wk, bk, K, M, D, D, 0, 0, 0, 1.0f);
    sgemm_kernel<true, true><<<gProj, 256>>>(source, Wv, bv, V, M, D, D, 0, 0, 0, 1.0f);

    // scores[b] = Q[b] @ K[b]^T / 32 : [2048, 2048], batched over 8
    dim3 gScore(SEQ / BN, SEQ / BM, BATCH);
    sgemm_kernel<true, false><<<gScore, 256>>>(
        Q, K, nullptr, S, SEQ, SEQ, D,
        (long long)SEQ * D, (long long)SEQ * D, (long long)SEQ * SEQ, 0.03125f);

    // softmax rows (B*T rows of length 2048), in place
    softmax_kernel<<<BATCH * SEQ, 256>>>(S);

    // ctx[b] = attn[b] @ V[b] : [2048, 1024], B is K-by-N (NN)
    dim3 gAV(D / BN, SEQ / BM, BATCH);
    sgemm_kernel<false, false><<<gAV, 256>>>(
        S, V, nullptr, C, SEQ, D, SEQ,
        (long long)SEQ * SEQ, (long long)SEQ * D, (long long)SEQ * D, 1.0f);

    // out = ctx @ Wo^T + bo
    sgemm_kernel<true, true><<<gProj, 256>>>(C, Wo, bo, out, M, D, D, 0, 0, 0, 1.0f);
}

// round 3
// speedup vs baseline: 1.9451x; 1.9451x over previous
#include <cuda_runtime.h>
#include <cuda_bf16.h>
#include <cstdint>
#include <math.h>

// ---------------------------------------------------------------------------
// CrossAttention B=8, T=S=2048, D=1024 (single head).
// R2: tcgen05 is ptxas-blocked at compute_103 (no 'a' features), so use the
// family-portable tensor path: mma.sync.m16n8k16 bf16 with split-bf16
// 3-product fp32 emulation. 128x128x32 tiles, swizzled smem, double buffer.
// ---------------------------------------------------------------------------

#define EMBED 1024
#define BATCH 8
#define SEQ   2048
#define MTOT  (BATCH * SEQ)

__device__ float g_Q [MTOT * EMBED];
__device__ float g_K [MTOT * EMBED];
__device__ float g_Vt[MTOT * EMBED];                 // [B][D][S]
__device__ float g_S [(long long)BATCH * SEQ * SEQ];
__device__ float g_C [MTOT * EMBED];

__device__ __forceinline__ uint32_t smem_u32(const void* p) {
    uint32_t a;
    asm("{ .reg .u64 t; cvta.to.shared.u64 t, %1; cvt.u32.u64 %0, t; }" : "=r"(a) : "l"(p));
    return a;
}

#define LDSM4(r, addr) \
    asm volatile("ldmatrix.sync.aligned.m8n8.x4.shared.b16 {%0,%1,%2,%3}, [%4];" \
        : "=r"((r)[0]), "=r"((r)[1]), "=r"((r)[2]), "=r"((r)[3]) : "r"(addr))

#define MMA(d, a, b) \
    asm volatile("mma.sync.aligned.m16n8k16.row.col.f32.bf16.bf16.f32 " \
        "{%0,%1,%2,%3}, {%4,%5,%6,%7}, {%8,%9}, {%0,%1,%2,%3};" \
        : "+f"((d)[0]), "+f"((d)[1]), "+f"((d)[2]), "+f"((d)[3]) \
        : "r"((a)[0]), "r"((a)[1]), "r"((a)[2]), "r"((a)[3]), "r"((b)[0]), "r"((b)[1]))

// fp32 x4,x4 -> bf16 hi uint4 + bf16 lo uint4 (memory order preserved)
__device__ __forceinline__ void cvt_split(float4 a, float4 b, uint4& hi, uint4& lo) {
    uint32_t h0, h1, h2, h3, l0, l1, l2, l3;
    asm("cvt.rn.bf16x2.f32 %0, %1, %2;" : "=r"(h0) : "f"(a.y), "f"(a.x));
    asm("cvt.rn.bf16x2.f32 %0, %1, %2;" : "=r"(h1) : "f"(a.w), "f"(a.z));
    asm("cvt.rn.bf16x2.f32 %0, %1, %2;" : "=r"(h2) : "f"(b.y), "f"(b.x));
    asm("cvt.rn.bf16x2.f32 %0, %1, %2;" : "=r"(h3) : "f"(b.w), "f"(b.z));
    float r0 = a.x - __uint_as_float(h0 << 16);
    float r1 = a.y - __uint_as_float(h0 & 0xFFFF0000u);
    float r2 = a.z - __uint_as_float(h1 << 16);
    float r3 = a.w - __uint_as_float(h1 & 0xFFFF0000u);
    float r4 = b.x - __uint_as_float(h2 << 16);
    float r5 = b.y - __uint_as_float(h2 & 0xFFFF0000u);
    float r6 = b.z - __uint_as_float(h3 << 16);
    float r7 = b.w - __uint_as_float(h3 & 0xFFFF0000u);
    asm("cvt.rn.bf16x2.f32 %0, %1, %2;" : "=r"(l0) : "f"(r1), "f"(r0));
    asm("cvt.rn.bf16x2.f32 %0, %1, %2;" : "=r"(l1) : "f"(r3), "f"(r2));
    asm("cvt.rn.bf16x2.f32 %0, %1, %2;" : "=r"(l2) : "f"(r5), "f"(r4));
    asm("cvt.rn.bf16x2.f32 %0, %1, %2;" : "=r"(l3) : "f"(r7), "f"(r6));
    hi = make_uint4(h0, h1, h2, h3);
    lo = make_uint4(l0, l1, l2, l3);
}

// Stage layout (32 KB): Ahi[0,8K) Alo[8K,16K) Bhi[16K,24K) Blo[24K,32K)
// Tile row = 32 bf16 = 64 B = 4 chunks of 16 B; swizzle: chunk ^= (row>>1)&3
#define STAGE_SZ 32768
#define SMEM_BYTES (2 * STAGE_SZ)

// C[M,N] = alpha * A[M,K] @ B[N,K]^T (+ bias[N]); TRANS=1: store to [B][D][S]
template <int HAS_BIAS, int TRANS>
__global__ __launch_bounds__(256, 1)
void mm_kernel(const float* __restrict__ A,
               const float* __restrict__ B,
               const float* __restrict__ bias,
               float* __restrict__ C,
               int M, int N, int K,
               long long sA, long long sB, long long sC,
               float alpha)
{
    extern __shared__ char sm[];
    const uint32_t sb = smem_u32(sm);
    const int tid  = threadIdx.x;
    const int lane = tid & 31;
    const int wid  = tid >> 5;
    const int wm   = wid >> 2;   // 0..1 : 64 rows each
    const int wn   = wid & 3;    // 0..3 : 32 cols each

    const float* Ab = A + blockIdx.z * sA + (long long)(blockIdx.y * 128) * K;
    const float* Bb = B + blockIdx.z * sB + (long long)(blockIdx.x * 128) * K;
    float*       Cb = C + blockIdx.z * sC;

    // ---- loader mapping: thread -> (row = tid>>2, chunk = tid&3) ----
    const int lr = tid >> 2;          // 0..63
    const int lc = tid & 3;           // 0..3
    const float* pA = Ab + (long long)lr * K + lc * 8;
    const float* pB = Bb + (long long)lr * K + lc * 8;
    const uint32_t soff = lr * 64 + ((lc ^ ((lr >> 1) & 3)) << 4);

    float4 v[8];
    auto ldg = [&](int kofs) {
        v[0] = *(const float4*)(pA + kofs);
        v[1] = *(const float4*)(pA + kofs + 4);
        v[2] = *(const float4*)(pA + kofs + (long long)64 * K);
        v[3] = *(const float4*)(pA + kofs + (long long)64 * K + 4);
        v[4] = *(const float4*)(pB + kofs);
        v[5] = *(const float4*)(pB + kofs + 4);
        v[6] = *(const float4*)(pB + kofs + (long long)64 * K);
        v[7] = *(const float4*)(pB + kofs + (long long)64 * K + 4);
    };
    auto sts = [&](int st) {
        char* stb = sm + st * STAGE_SZ;
        uint4 hi, lo;
        cvt_split(v[0], v[1], hi, lo);
        *(uint4*)(stb + soff)            = hi;  *(uint4*)(stb + 8192  + soff)        = lo;
        cvt_split(v[2], v[3], hi, lo);
        *(uint4*)(stb + soff + 4096)     = hi;  *(uint4*)(stb + 8192  + soff + 4096) = lo;
        cvt_split(v[4], v[5], hi, lo);
        *(uint4*)(stb + 16384 + soff)    = hi;  *(uint4*)(stb + 24576 + soff)        = lo;
        cvt_split(v[6], v[7], hi, lo);
        *(uint4*)(stb + 16384 + soff + 4096) = hi; *(uint4*)(stb + 24576 + soff + 4096) = lo;
    };

    // ---- ldmatrix per-lane addressing ----
    const int g      = lane >> 3;
    const int rr     = lane & 7;
    const int rowoff = ((g & 1) << 3) + rr;       // 0..15
    const int csel   = g >> 1;                    // 0..1
    const int sw     = (rowoff >> 1) & 3;
    uint32_t aRowB[4], bRowB[2];
#pragma unroll
    for (int mt = 0; mt < 4; mt++) aRowB[mt] = (wm * 64 + mt * 16 + rowoff) * 64;
#pragma unroll
    for (int pr = 0; pr < 2; pr++) bRowB[pr] = (wn * 32 + pr * 16 + rowoff) * 64;

    float cacc[4][4][4];
#pragma unroll
    for (int i = 0; i < 4; i++)
#pragma unroll
        for (int j = 0; j < 4; j++)
#pragma unroll
            for (int q = 0; q < 4; q++) cacc[i][j][q] = 0.0f;

    auto compute = [&](int st) {
        const uint32_t stg = sb + st * STAGE_SZ;
#pragma unroll
        for (int s = 0; s < 2; s++) {
            uint32_t ah[4][4], al[4][4], bh[4][2], bl[4][2];
            const uint32_t ck = ((2 * s + csel) ^ sw) << 4;
#pragma unroll
            for (int mt = 0; mt < 4; mt++) {
                LDSM4(ah[mt], stg + aRowB[mt] + ck);
                LDSM4(al[mt], stg + 8192 + aRowB[mt] + ck);
            }
#pragma unroll
            for (int pr = 0; pr < 2; pr++) {
                uint32_t t[4];
                LDSM4(t, stg + 16384 + bRowB[pr] + ck);
                bh[2 * pr][0] = t[0]; bh[2 * pr + 1][0] = t[1];
                bh[2 * pr][1] = t[2]; bh[2 * pr + 1][1] = t[3];
                LDSM4(t, stg + 24576 + bRowB[pr] + ck);
                bl[2 * pr][0] = t[0]; bl[2 * pr + 1][0] = t[1];
                bl[2 * pr][1] = t[2]; bl[2 * pr + 1][1] = t[3];
            }
#pragma unroll
            for (int mt = 0; mt < 4; mt++)
#pragma unroll
                for (int nt = 0; nt < 4; nt++) {
                    MMA(cacc[mt][nt], ah[mt], bh[nt]);
                    MMA(cacc[mt][nt], ah[mt], bl[nt]);
                    MMA(cacc[mt][nt], al[mt], bh[nt]);
                }
        }
    };

    const int NC = K >> 5;
    ldg(0);
    sts(0);
    __syncthreads();
    for (int c = 0; c < NC; c++) {
        if (c + 1 < NC) ldg((c + 1) << 5);
        compute(c & 1);
        if (c + 1 < NC) sts((c + 1) & 1);
        __syncthreads();
    }

    // ---- epilogue ----
    const int l4 = lane >> 2;
    const int l2 = (lane & 3) * 2;
#pragma unroll
    for (int mt = 0; mt < 4; mt++) {
        const int mg = blockIdx.y * 128 + wm * 64 + mt * 16 + l4;
        if (!TRANS) {
#pragma unroll
            for (int nt = 0; nt < 4; nt++) {
                const int n = blockIdx.x * 128 + wn * 32 + nt * 8 + l2;
                float b0 = 0.f, b1 = 0.f;
                if (HAS_BIAS) { b0 = bias[n]; b1 = bias[n + 1]; }
                float2 o0, o1;
                o0.x = cacc[mt][nt][0] * alpha + b0;
                o0.y = cacc[mt][nt][1] * alpha + b1;
                o1.x = cacc[mt][nt][2] * alpha + b0;
                o1.y = cacc[mt][nt][3] * alpha + b1;
                *(float2*)&Cb[(long long)mg * N + n]       = o0;
                *(float2*)&Cb[(long long)(mg + 8) * N + n] = o1;
            }
        } else {
            const int b  = mg >> 11;
            const int s2 = mg & 2047;
            float* cb = Cb + (long long)b * EMBED * SEQ + s2;
#pragma unroll
            for (int nt = 0; nt < 4; nt++) {
                const int n = blockIdx.x * 128 + wn * 32 + nt * 8 + l2;
                float b0 = 0.f, b1 = 0.f;
                if (HAS_BIAS) { b0 = bias[n]; b1 = bias[n + 1]; }
                cb[(long long)n * SEQ]           = cacc[mt][nt][0] * alpha + b0;
                cb[(long long)(n + 1) * SEQ]     = cacc[mt][nt][1] * alpha + b1;
                cb[(long long)n * SEQ + 8]       = cacc[mt][nt][2] * alpha + b0;
                cb[(long long)(n + 1) * SEQ + 8] = cacc[mt][nt][3] * alpha + b1;
            }
        }
    }
}

// ---------------------------------------------------------------------------
// Row softmax over 2048 columns, one block (256 threads) per row, in place.
// ---------------------------------------------------------------------------
__global__ __launch_bounds__(256)
void softmax_kernel(float* __restrict__ S)
{
    float* row = S + (long long)blockIdx.x * SEQ;
    const int t = threadIdx.x;
    const int lane = t & 31;
    const int wid  = t >> 5;

    float4 v0 = ((const float4*)row)[t];
    float4 v1 = ((const float4*)row)[t + 256];

    float m = fmaxf(fmaxf(fmaxf(v0.x, v0.y), fmaxf(v0.z, v0.w)),
                    fmaxf(fmaxf(v1.x, v1.y), fmaxf(v1.z, v1.w)));
#pragma unroll
    for (int o = 16; o > 0; o >>= 1)
        m = fmaxf(m, __shfl_xor_sync(0xFFFFFFFFu, m, o));

    __shared__ float red[8];
    if (lane == 0) red[wid] = m;
    __syncthreads();
    float M = red[0];
#pragma unroll
    for (int i = 1; i < 8; i++) M = fmaxf(M, red[i]);
    __syncthreads();

    v0.x = __expf(v0.x - M); v0.y = __expf(v0.y - M);
    v0.z = __expf(v0.z - M); v0.w = __expf(v0.w - M);
    v1.x = __expf(v1.x - M); v1.y = __expf(v1.y - M);
    v1.z = __expf(v1.z - M); v1.w = __expf(v1.w - M);

    float s = (v0.x + v0.y + v0.z + v0.w) + (v1.x + v1.y + v1.z + v1.w);
#pragma unroll
    for (int o = 16; o > 0; o >>= 1)
        s += __shfl_xor_sync(0xFFFFFFFFu, s, o);
    if (lane == 0) red[wid] = s;
    __syncthreads();
    float Ssum = 0.0f;
#pragma unroll
    for (int i = 0; i < 8; i++) Ssum += red[i];

    float inv = 1.0f / Ssum;
    v0.x *= inv; v0.y *= inv; v0.z *= inv; v0.w *= inv;
    v1.x *= inv; v1.y *= inv; v1.z *= inv; v1.w *= inv;

    ((float4*)row)[t]       = v0;
    ((float4*)row)[t + 256] = v1;
}

extern "C" void kernel_launch(void* const* d_in, const int* in_sizes, int n_in,
                              void* d_out, int out_size)
{
    const float* target = (const float*)d_in[0];
    const float* source = (const float*)d_in[1];
    const float* Wq     = (const float*)d_in[2];
    const float* bq     = (const float*)d_in[3];
    const float* Wk     = (const float*)d_in[4];
    const float* bk     = (const float*)d_in[5];
    const float* Wv     = (const float*)d_in[6];
    const float* bv     = (const float*)d_in[7];
    const float* Wo     = (const float*)d_in[8];
    const float* bo     = (const float*)d_in[9];
    float* out = (float*)d_out;

    float *Q, *Kp, *Vt, *S, *C;
    cudaGetSymbolAddress((void**)&Q,  g_Q);
    cudaGetSymbolAddress((void**)&Kp, g_K);
    cudaGetSymbolAddress((void**)&Vt, g_Vt);
    cudaGetSymbolAddress((void**)&S,  g_S);
    cudaGetSymbolAddress((void**)&C,  g_C);

    cudaFuncSetAttribute(mm_kernel<1, 0>, cudaFuncAttributeMaxDynamicSharedMemorySize, SMEM_BYTES);
    cudaFuncSetAttribute(mm_kernel<1, 1>, cudaFuncAttributeMaxDynamicSharedMemorySize, SMEM_BYTES);
    cudaFuncSetAttribute(mm_kernel<0, 0>, cudaFuncAttributeMaxDynamicSharedMemorySize, SMEM_BYTES);

    dim3 gProj(EMBED / 128, MTOT / 128, 1);
    mm_kernel<1, 0><<<gProj, 256, SMEM_BYTES>>>(target, Wq, bq, Q,  MTOT, EMBED, EMBED, 0, 0, 0, 1.0f);
    mm_kernel<1, 0><<<gProj, 256, SMEM_BYTES>>>(source, Wk, bk, Kp, MTOT, EMBED, EMBED, 0, 0, 0, 1.0f);
    mm_kernel<1, 1><<<gProj, 256, SMEM_BYTES>>>(source, Wv, bv, Vt, MTOT, EMBED, EMBED, 0, 0, 0, 1.0f);

    dim3 gScore(SEQ / 128, SEQ / 128, BATCH);
    mm_kernel<0, 0><<<gScore, 256, SMEM_BYTES>>>(
        Q, Kp, nullptr, S, SEQ, SEQ, EMBED,
        (long long)SEQ * EMBED, (long long)SEQ * EMBED, (long long)SEQ * SEQ, 0.03125f);

    softmax_kernel<<<BATCH * SEQ, 256>>>(S);

    dim3 gAV(EMBED / 128, SEQ / 128, BATCH);
    mm_kernel<0, 0><<<gAV, 256, SMEM_BYTES>>>(
        S, Vt, nullptr, C, SEQ, EMBED, SEQ,
        (long long)SEQ * SEQ, (long long)EMBED * SEQ, (long long)SEQ * EMBED, 1.0f);

    mm_kernel<1, 0><<<gProj, 256, SMEM_BYTES>>>(C, Wo, bo, out, MTOT, EMBED, EMBED, 0, 0, 0, 1.0f);
}

// round 4
// speedup vs baseline: 1.9561x; 1.0056x over previous
#include <cuda_runtime.h>
#include <cuda_bf16.h>
#include <cstdint>
#include <math.h>

// ---------------------------------------------------------------------------
// CrossAttention B=8, T=S=2048, D=1024 (single head).
// R3: all operands pre-split into hi/lo bf16 in gmem. GEMM = cp.async 4-stage
// pipeline -> ldmatrix -> mma.sync m16n8k16 (3-product split-bf16 fp32 emu).
// ---------------------------------------------------------------------------

#define EMBED 1024
#define BATCH 8
#define SEQ   2048
#define MTOT  (BATCH * SEQ)

typedef __nv_bfloat16 bf16;

// fp32 scratch
__device__ float g_Sc[(long long)BATCH * SEQ * SEQ];   // scores (fp32)
// hi/lo bf16 operands
__device__ bf16 g_Thi[MTOT * EMBED], g_Tlo[MTOT * EMBED];     // target
__device__ bf16 g_Shi[MTOT * EMBED], g_Slo[MTOT * EMBED];     // source
__device__ bf16 g_Wqhi[EMBED * EMBED], g_Wqlo[EMBED * EMBED];
__device__ bf16 g_Wkhi[EMBED * EMBED], g_Wklo[EMBED * EMBED];
__device__ bf16 g_Wvhi[EMBED * EMBED], g_Wvlo[EMBED * EMBED];
__device__ bf16 g_Wohi[EMBED * EMBED], g_Wolo[EMBED * EMBED];
__device__ bf16 g_Qhi[MTOT * EMBED],  g_Qlo[MTOT * EMBED];
__device__ bf16 g_Khi[MTOT * EMBED],  g_Klo[MTOT * EMBED];
__device__ bf16 g_Vthi[MTOT * EMBED], g_Vtlo[MTOT * EMBED];   // [B][D][S]
__device__ bf16 g_Phi[(long long)BATCH * SEQ * SEQ], g_Plo[(long long)BATCH * SEQ * SEQ]; // attn
__device__ bf16 g_Chi[MTOT * EMBED],  g_Clo[MTOT * EMBED];    // ctx

__device__ __forceinline__ uint32_t smem_u32(const void* p) {
    uint32_t a;
    asm("{ .reg .u64 t; cvta.to.shared.u64 t, %1; cvt.u32.u64 %0, t; }" : "=r"(a) : "l"(p));
    return a;
}

#define LDSM4(r, addr) \
    asm volatile("ldmatrix.sync.aligned.m8n8.x4.shared.b16 {%0,%1,%2,%3}, [%4];" \
        : "=r"((r)[0]), "=r"((r)[1]), "=r"((r)[2]), "=r"((r)[3]) : "r"(addr))

#define MMA(d, a, b) \
    asm volatile("mma.sync.aligned.m16n8k16.row.col.f32.bf16.bf16.f32 " \
        "{%0,%1,%2,%3}, {%4,%5,%6,%7}, {%8,%9}, {%0,%1,%2,%3};" \
        : "+f"((d)[0]), "+f"((d)[1]), "+f"((d)[2]), "+f"((d)[3]) \
        : "r"((a)[0]), "r"((a)[1]), "r"((a)[2]), "r"((a)[3]), "r"((b)[0]), "r"((b)[1]))

#define CP16(dst, src) \
    asm volatile("cp.async.cg.shared.global [%0], [%1], 16;" :: "r"(dst), "l"(src))
#define CP_COMMIT() asm volatile("cp.async.commit_group;" ::: "memory")
#define CP_WAIT2()  asm volatile("cp.async.wait_group 2;" ::: "memory")

// two fp32 -> packed bf16 hi pair + packed bf16 residual pair
__device__ __forceinline__ void split2(float f0, float f1, uint32_t& hi, uint32_t& lo) {
    asm("cvt.rn.bf16x2.f32 %0, %1, %2;" : "=r"(hi) : "f"(f1), "f"(f0));
    float r0 = f0 - __uint_as_float(hi << 16);
    float r1 = f1 - __uint_as_float(hi & 0xFFFF0000u);
    asm("cvt.rn.bf16x2.f32 %0, %1, %2;" : "=r"(lo) : "f"(r1), "f"(r0));
}

// Stage (32 KB): Ahi[0,8K) Alo[8K,16K) Bhi[16K,24K) Blo[24K,32K)
// Row = 64 B (32 bf16) = 4 x 16B chunks; swizzle: chunk ^= (row>>1)&3
#define STAGE_SZ 32768
#define STAGES   4
#define SMEM_BYTES (STAGES * STAGE_SZ)

// C = alpha * A @ B^T (+bias). EPI: 0=fp32 out, 1=hi/lo bf16 out, 2=hi/lo transposed ([B][D][S])
template <int HAS_BIAS, int EPI>
__global__ __launch_bounds__(256, 1)
void mm_kernel(const bf16* __restrict__ Ahi, const bf16* __restrict__ Alo,
               const bf16* __restrict__ Bhi, const bf16* __restrict__ Blo,
               const float* __restrict__ bias,
               float* __restrict__ Cf, bf16* __restrict__ Chi, bf16* __restrict__ Clo,
               int M, int N, int K,
               long long sA, long long sB, long long sC, float alpha)
{
    extern __shared__ char sm[];
    const uint32_t sb = smem_u32(sm);
    const int tid  = threadIdx.x;
    const int lane = tid & 31;
    const int wid  = tid >> 5;
    const int wm   = wid >> 2;
    const int wn   = wid & 3;

    const long long aoff = blockIdx.z * sA + (long long)(blockIdx.y * 128) * K;
    const long long boff = blockIdx.z * sB + (long long)(blockIdx.x * 128) * K;

    // ---- cp.async loader: tid -> row=tid>>1, two 16B chunks ----
    const int lrow = tid >> 1;
    const int c0   = (tid & 1) * 2;
    const int swl  = (lrow >> 1) & 3;
    const uint32_t d0 = lrow * 64 + ((c0 ^ swl) << 4);
    const uint32_t d1 = lrow * 64 + (((c0 + 1) ^ swl) << 4);
    const bf16* pAhi = Ahi + aoff + (long long)lrow * K + c0 * 8;
    const bf16* pAlo = Alo + aoff + (long long)lrow * K + c0 * 8;
    const bf16* pBhi = Bhi + boff + (long long)lrow * K + c0 * 8;
    const bf16* pBlo = Blo + boff + (long long)lrow * K + c0 * 8;

    auto load_stage = [&](int kofs, int st) {
        const uint32_t stb = sb + st * STAGE_SZ;
        CP16(stb + d0,         pAhi + kofs);
        CP16(stb + d1,         pAhi + kofs + 8);
        CP16(stb + 8192  + d0, pAlo + kofs);
        CP16(stb + 8192  + d1, pAlo + kofs + 8);
        CP16(stb + 16384 + d0, pBhi + kofs);
        CP16(stb + 16384 + d1, pBhi + kofs + 8);
        CP16(stb + 24576 + d0, pBlo + kofs);
        CP16(stb + 24576 + d1, pBlo + kofs + 8);
    };

    // ---- ldmatrix addressing ----
    const int g      = lane >> 3;
    const int rr     = lane & 7;
    const int rowoff = ((g & 1) << 3) + rr;
    const int csel   = g >> 1;
    const int sw     = (rowoff >> 1) & 3;
    uint32_t aRowB[4], bRowB[2];
#pragma unroll
    for (int mt = 0; mt < 4; mt++) aRowB[mt] = (wm * 64 + mt * 16 + rowoff) * 64;
#pragma unroll
    for (int pr = 0; pr < 2; pr++) bRowB[pr] = (wn * 32 + pr * 16 + rowoff) * 64;

    float cacc[4][4][4];
#pragma unroll
    for (int i = 0; i < 4; i++)
#pragma unroll
        for (int j = 0; j < 4; j++)
#pragma unroll
            for (int q = 0; q < 4; q++) cacc[i][j][q] = 0.0f;

    auto compute = [&](int st) {
        const uint32_t stg = sb + st * STAGE_SZ;
#pragma unroll
        for (int s = 0; s < 2; s++) {
            uint32_t ah[4][4], al[4][4], bh[4][2], bl[4][2];
            const uint32_t ck = ((2 * s + csel) ^ sw) << 4;
#pragma unroll
            for (int mt = 0; mt < 4; mt++) {
                LDSM4(ah[mt], stg + aRowB[mt] + ck);
                LDSM4(al[mt], stg + 8192 + aRowB[mt] + ck);
            }
#pragma unroll
            for (int pr = 0; pr < 2; pr++) {
                uint32_t t[4];
                LDSM4(t, stg + 16384 + bRowB[pr] + ck);
                bh[2 * pr][0] = t[0]; bh[2 * pr + 1][0] = t[1];
                bh[2 * pr][1] = t[2]; bh[2 * pr + 1][1] = t[3];
                LDSM4(t, stg + 24576 + bRowB[pr] + ck);
                bl[2 * pr][0] = t[0]; bl[2 * pr + 1][0] = t[1];
                bl[2 * pr][1] = t[2]; bl[2 * pr + 1][1] = t[3];
            }
#pragma unroll
            for (int mt = 0; mt < 4; mt++)
#pragma unroll
                for (int nt = 0; nt < 4; nt++) {
                    MMA(cacc[mt][nt], ah[mt], bh[nt]);
                    MMA(cacc[mt][nt], ah[mt], bl[nt]);
                    MMA(cacc[mt][nt], al[mt], bh[nt]);
                }
        }
    };

    const int NC = K >> 5;
    load_stage(0, 0);  CP_COMMIT();
    load_stage(32, 1); CP_COMMIT();
    load_stage(64, 2); CP_COMMIT();

    for (int c = 0; c < NC; c++) {
        CP_WAIT2();
        __syncthreads();
        if (c + 3 < NC) load_stage((c + 3) << 5, (c + 3) & 3);
        CP_COMMIT();
        compute(c & 3);
    }

    // ---- epilogue ----
    const int l4 = lane >> 2;
    const int l2 = (lane & 3) * 2;
#pragma unroll
    for (int mt = 0; mt < 4; mt++) {
        const int mg = blockIdx.y * 128 + wm * 64 + mt * 16 + l4;
#pragma unroll
        for (int nt = 0; nt < 4; nt++) {
            const int n = blockIdx.x * 128 + wn * 32 + nt * 8 + l2;
            float b0 = 0.f, b1 = 0.f;
            if (HAS_BIAS) { b0 = bias[n]; b1 = bias[n + 1]; }
            float f0 = cacc[mt][nt][0] * alpha + b0;
            float f1 = cacc[mt][nt][1] * alpha + b1;
            float f2 = cacc[mt][nt][2] * alpha + b0;
            float f3 = cacc[mt][nt][3] * alpha + b1;
            if (EPI == 0) {
                float* cb = Cf + blockIdx.z * sC;
                *(float2*)&cb[(long long)mg * N + n]       = make_float2(f0, f1);
                *(float2*)&cb[(long long)(mg + 8) * N + n] = make_float2(f2, f3);
            } else if (EPI == 1) {
                uint32_t h, l;
                split2(f0, f1, h, l);
                *(uint32_t*)&Chi[blockIdx.z * sC + (long long)mg * N + n] = h;
                *(uint32_t*)&Clo[blockIdx.z * sC + (long long)mg * N + n] = l;
                split2(f2, f3, h, l);
                *(uint32_t*)&Chi[blockIdx.z * sC + (long long)(mg + 8) * N + n] = h;
                *(uint32_t*)&Clo[blockIdx.z * sC + (long long)(mg + 8) * N + n] = l;
            } else {
                // transposed: row m -> (b, s), col n -> Vt[b][n][s]
                const int b  = mg >> 11;
                const int s2 = mg & 2047;
                bf16* vh = Chi + (long long)b * EMBED * SEQ + s2;
                bf16* vl = Clo + (long long)b * EMBED * SEQ + s2;
                uint32_t h, l;
                split2(f0, f1, h, l);
                vh[(long long)n * SEQ]       = __ushort_as_bfloat16((unsigned short)(h & 0xFFFF));
                vh[(long long)(n + 1) * SEQ] = __ushort_as_bfloat16((unsigned short)(h >> 16));
                vl[(long long)n * SEQ]       = __ushort_as_bfloat16((unsigned short)(l & 0xFFFF));
                vl[(long long)(n + 1) * SEQ] = __ushort_as_bfloat16((unsigned short)(l >> 16));
                split2(f2, f3, h, l);
                vh[(long long)n * SEQ + 8]       = __ushort_as_bfloat16((unsigned short)(h & 0xFFFF));
                vh[(long long)(n + 1) * SEQ + 8] = __ushort_as_bfloat16((unsigned short)(h >> 16));
                vl[(long long)n * SEQ + 8]       = __ushort_as_bfloat16((unsigned short)(l & 0xFFFF));
                vl[(long long)(n + 1) * SEQ + 8] = __ushort_as_bfloat16((unsigned short)(l >> 16));
            }
        }
    }
}

// ---------------------------------------------------------------------------
// Softmax over 2048 cols; reads fp32 scores, writes attn as hi/lo bf16.
// ---------------------------------------------------------------------------
__global__ __launch_bounds__(256)
void softmax_kernel(const float* __restrict__ S, bf16* __restrict__ Phi, bf16* __restrict__ Plo)
{
    const float* row = S + (long long)blockIdx.x * SEQ;
    const int t = threadIdx.x;
    const int lane = t & 31;
    const int wid  = t >> 5;

    float4 v0 = ((const float4*)row)[t];
    float4 v1 = ((const float4*)row)[t + 256];

    float m = fmaxf(fmaxf(fmaxf(v0.x, v0.y), fmaxf(v0.z, v0.w)),
                    fmaxf(fmaxf(v1.x, v1.y), fmaxf(v1.z, v1.w)));
#pragma unroll
    for (int o = 16; o > 0; o >>= 1)
        m = fmaxf(m, __shfl_xor_sync(0xFFFFFFFFu, m, o));

    __shared__ float red[8];
    if (lane == 0) red[wid] = m;
    __syncthreads();
    float M = red[0];
#pragma unroll
    for (int i = 1; i < 8; i++) M = fmaxf(M, red[i]);
    __syncthreads();

    v0.x = __expf(v0.x - M); v0.y = __expf(v0.y - M);
    v0.z = __expf(v0.z - M); v0.w = __expf(v0.w - M);
    v1.x = __expf(v1.x - M); v1.y = __expf(v1.y - M);
    v1.z = __expf(v1.z - M); v1.w = __expf(v1.w - M);

    float s = (v0.x + v0.y + v0.z + v0.w) + (v1.x + v1.y + v1.z + v1.w);
#pragma unroll
    for (int o = 16; o > 0; o >>= 1)
        s += __shfl_xor_sync(0xFFFFFFFFu, s, o);
    if (lane == 0) red[wid] = s;
    __syncthreads();
    float Ssum = 0.0f;
#pragma unroll
    for (int i = 0; i < 8; i++) Ssum += red[i];

    const float inv = 1.0f / Ssum;
    v0.x *= inv; v0.y *= inv; v0.z *= inv; v0.w *= inv;
    v1.x *= inv; v1.y *= inv; v1.z *= inv; v1.w *= inv;

    uint2* ph = (uint2*)(Phi + (long long)blockIdx.x * SEQ);
    uint2* pl = (uint2*)(Plo + (long long)blockIdx.x * SEQ);
    uint32_t h01, l01, h23, l23;
    split2(v0.x, v0.y, h01, l01); split2(v0.z, v0.w, h23, l23);
    ph[t] = make_uint2(h01, h23); pl[t] = make_uint2(l01, l23);
    split2(v1.x, v1.y, h01, l01); split2(v1.z, v1.w, h23, l23);
    ph[t + 256] = make_uint2(h01, h23); pl[t + 256] = make_uint2(l01, l23);
}

// elementwise fp32 -> hi/lo bf16 (vectorized x4)
__global__ __launch_bounds__(256)
void cvt_kernel(const float* __restrict__ src, bf16* __restrict__ hi, bf16* __restrict__ lo, int n4)
{
    int i = blockIdx.x * blockDim.x + threadIdx.x;
    if (i >= n4) return;
    float4 v = ((const float4*)src)[i];
    uint32_t h01, l01, h23, l23;
    split2(v.x, v.y, h01, l01);
    split2(v.z, v.w, h23, l23);
    ((uint2*)hi)[i] = make_uint2(h01, h23);
    ((uint2*)lo)[i] = make_uint2(l01, l23);
}

extern "C" void kernel_launch(void* const* d_in, const int* in_sizes, int n_in,
                              void* d_out, int out_size)
{
    const float* target = (const float*)d_in[0];
    const float* source = (const float*)d_in[1];
    const float* Wq     = (const float*)d_in[2];
    const float* bq     = (const float*)d_in[3];
    const float* Wk     = (const float*)d_in[4];
    const float* bk     = (const float*)d_in[5];
    const float* Wv     = (const float*)d_in[6];
    const float* bv     = (const float*)d_in[7];
    const float* Wo     = (const float*)d_in[8];
    const float* bo     = (const float*)d_in[9];
    float* out = (float*)d_out;

    float* Sc;
    cudaGetSymbolAddress((void**)&Sc, g_Sc);
    bf16 *Thi,*Tlo,*Shi,*Slo,*Wqh,*Wql,*Wkh,*Wkl,*Wvh,*Wvl,*Woh,*Wol;
    bf16 *Qhi,*Qlo,*Khi,*Klo,*Vth,*Vtl,*Phi,*Plo,*Chi,*Clo;
    cudaGetSymbolAddress((void**)&Thi, g_Thi);  cudaGetSymbolAddress((void**)&Tlo, g_Tlo);
    cudaGetSymbolAddress((void**)&Shi, g_Shi);  cudaGetSymbolAddress((void**)&Slo, g_Slo);
    cudaGetSymbolAddress((void**)&Wqh, g_Wqhi); cudaGetSymbolAddress((void**)&Wql, g_Wqlo);
    cudaGetSymbolAddress((void**)&Wkh, g_Wkhi); cudaGetSymbolAddress((void**)&Wkl, g_Wklo);
    cudaGetSymbolAddress((void**)&Wvh, g_Wvhi); cudaGetSymbolAddress((void**)&Wvl, g_Wvlo);
    cudaGetSymbolAddress((void**)&Woh, g_Wohi); cudaGetSymbolAddress((void**)&Wol, g_Wolo);
    cudaGetSymbolAddress((void**)&Qhi, g_Qhi);  cudaGetSymbolAddress((void**)&Qlo, g_Qlo);
    cudaGetSymbolAddress((void**)&Khi, g_Khi);  cudaGetSymbolAddress((void**)&Klo, g_Klo);
    cudaGetSymbolAddress((void**)&Vth, g_Vthi); cudaGetSymbolAddress((void**)&Vtl, g_Vtlo);
    cudaGetSymbolAddress((void**)&Phi, g_Phi);  cudaGetSymbolAddress((void**)&Plo, g_Plo);
    cudaGetSymbolAddress((void**)&Chi, g_Chi);  cudaGetSymbolAddress((void**)&Clo, g_Clo);

    cudaFuncSetAttribute(mm_kernel<1, 1>, cudaFuncAttributeMaxDynamicSharedMemorySize, SMEM_BYTES);
    cudaFuncSetAttribute(mm_kernel<1, 2>, cudaFuncAttributeMaxDynamicSharedMemorySize, SMEM_BYTES);
    cudaFuncSetAttribute(mm_kernel<0, 0>, cudaFuncAttributeMaxDynamicSharedMemorySize, SMEM_BYTES);
    cudaFuncSetAttribute(mm_kernel<0, 1>, cudaFuncAttributeMaxDynamicSharedMemorySize, SMEM_BYTES);
    cudaFuncSetAttribute(mm_kernel<1, 0>, cudaFuncAttributeMaxDynamicSharedMemorySize, SMEM_BYTES);

    // ---- input conversion ----
    const int nIn  = MTOT * EMBED / 4;    // 4.19M float4s
    const int nW   = EMBED * EMBED / 4;
    cvt_kernel<<<(nIn + 255) / 256, 256>>>(target, Thi, Tlo, nIn);
    cvt_kernel<<<(nIn + 255) / 256, 256>>>(source, Shi, Slo, nIn);
    cvt_kernel<<<(nW + 255) / 256, 256>>>(Wq, Wqh, Wql, nW);
    cvt_kernel<<<(nW + 255) / 256, 256>>>(Wk, Wkh, Wkl, nW);
    cvt_kernel<<<(nW + 255) / 256, 256>>>(Wv, Wvh, Wvl, nW);
    cvt_kernel<<<(nW + 255) / 256, 256>>>(Wo, Woh, Wol, nW);

    // ---- projections ----
    dim3 gProj(EMBED / 128, MTOT / 128, 1);
    mm_kernel<1, 1><<<gProj, 256, SMEM_BYTES>>>(Thi, Tlo, Wqh, Wql, bq, nullptr, Qhi, Qlo,
                                                MTOT, EMBED, EMBED, 0, 0, 0, 1.0f);
    mm_kernel<1, 1><<<gProj, 256, SMEM_BYTES>>>(Shi, Slo, Wkh, Wkl, bk, nullptr, Khi, Klo,
                                                MTOT, EMBED, EMBED, 0, 0, 0, 1.0f);
    mm_kernel<1, 2><<<gProj, 256, SMEM_BYTES>>>(Shi, Slo, Wvh, Wvl, bv, nullptr, Vth, Vtl,
                                                MTOT, EMBED, EMBED, 0, 0, 0, 1.0f);

    // ---- scores = Q K^T / 32 ----
    dim3 gScore(SEQ / 128, SEQ / 128, BATCH);
    mm_kernel<0, 0><<<gScore, 256, SMEM_BYTES>>>(Qhi, Qlo, Khi, Klo, nullptr, Sc, nullptr, nullptr,
                                                 SEQ, SEQ, EMBED,
                                                 (long long)SEQ * EMBED, (long long)SEQ * EMBED,
                                                 (long long)SEQ * SEQ, 0.03125f);

    softmax_kernel<<<BATCH * SEQ, 256>>>(Sc, Phi, Plo);

    // ---- ctx = attn @ V ----
    dim3 gAV(EMBED / 128, SEQ / 128, BATCH);
    mm_kernel<0, 1><<<gAV, 256, SMEM_BYTES>>>(Phi, Plo, Vth, Vtl, nullptr, nullptr, Chi, Clo,
                                              SEQ, EMBED, SEQ,
                                              (long long)SEQ * SEQ, (long long)EMBED * SEQ,
                                              (long long)SEQ * EMBED, 1.0f);

    // ---- out = ctx @ Wo^T + bo ----
    mm_kernel<1, 0><<<gProj, 256, SMEM_BYTES>>>(Chi, Clo, Woh, Wol, bo, out, nullptr, nullptr,
                                                MTOT, EMBED, EMBED, 0, 0, 0, 1.0f);
}

// round 5
// speedup vs baseline: 2.0386x; 1.0422x over previous
#include <cuda_runtime.h>
#include <cuda_bf16.h>
#include <cstdint>
#include <math.h>

// ---------------------------------------------------------------------------
// CrossAttention B=8, T=S=2048, D=1024 (single head).
// R4: split-bf16 3-product fp32-emulated GEMMs on mma.sync m16n8k16.
// 128x128 CTA tile, K=64 smem stages (3-deep cp.async), register-fragment
// double buffering to overlap ldmatrix with MMA.
// ---------------------------------------------------------------------------

#define EMBED 1024
#define BATCH 8
#define SEQ   2048
#define MTOT  (BATCH * SEQ)

typedef __nv_bfloat16 bf16;

__device__ float g_Sc[(long long)BATCH * SEQ * SEQ];   // scores (fp32)
__device__ bf16 g_Thi[MTOT * EMBED], g_Tlo[MTOT * EMBED];
__device__ bf16 g_Shi[MTOT * EMBED], g_Slo[MTOT * EMBED];
__device__ bf16 g_Wqhi[EMBED * EMBED], g_Wqlo[EMBED * EMBED];
__device__ bf16 g_Wkhi[EMBED * EMBED], g_Wklo[EMBED * EMBED];
__device__ bf16 g_Wvhi[EMBED * EMBED], g_Wvlo[EMBED * EMBED];
__device__ bf16 g_Wohi[EMBED * EMBED], g_Wolo[EMBED * EMBED];
__device__ bf16 g_Qhi[MTOT * EMBED],  g_Qlo[MTOT * EMBED];
__device__ bf16 g_Khi[MTOT * EMBED],  g_Klo[MTOT * EMBED];
__device__ bf16 g_Vthi[MTOT * EMBED], g_Vtlo[MTOT * EMBED];   // [B][D][S]
__device__ bf16 g_Phi[(long long)BATCH * SEQ * SEQ], g_Plo[(long long)BATCH * SEQ * SEQ];
__device__ bf16 g_Chi[MTOT * EMBED],  g_Clo[MTOT * EMBED];

__device__ __forceinline__ uint32_t smem_u32(const void* p) {
    uint32_t a;
    asm("{ .reg .u64 t; cvta.to.shared.u64 t, %1; cvt.u32.u64 %0, t; }" : "=r"(a) : "l"(p));
    return a;
}

#define LDSM4(r, addr) \
    asm volatile("ldmatrix.sync.aligned.m8n8.x4.shared.b16 {%0,%1,%2,%3}, [%4];" \
        : "=r"((r)[0]), "=r"((r)[1]), "=r"((r)[2]), "=r"((r)[3]) : "r"(addr))

#define MMA(d, a, b) \
    asm volatile("mma.sync.aligned.m16n8k16.row.col.f32.bf16.bf16.f32 " \
        "{%0,%1,%2,%3}, {%4,%5,%6,%7}, {%8,%9}, {%0,%1,%2,%3};" \
        : "+f"((d)[0]), "+f"((d)[1]), "+f"((d)[2]), "+f"((d)[3]) \
        : "r"((a)[0]), "r"((a)[1]), "r"((a)[2]), "r"((a)[3]), "r"((b)[0]), "r"((b)[1]))

#define CP16(dst, src) \
    asm volatile("cp.async.cg.shared.global [%0], [%1], 16;" :: "r"(dst), "l"(src))
#define CP_COMMIT() asm volatile("cp.async.commit_group;" ::: "memory")
#define CP_WAIT1()  asm volatile("cp.async.wait_group 1;" ::: "memory")

__device__ __forceinline__ void split2(float f0, float f1, uint32_t& hi, uint32_t& lo) {
    asm("cvt.rn.bf16x2.f32 %0, %1, %2;" : "=r"(hi) : "f"(f1), "f"(f0));
    float r0 = f0 - __uint_as_float(hi << 16);
    float r1 = f1 - __uint_as_float(hi & 0xFFFF0000u);
    asm("cvt.rn.bf16x2.f32 %0, %1, %2;" : "=r"(lo) : "f"(r1), "f"(r0));
}

// Stage (64 KB): Ahi[0,16K) Alo[16K,32K) Bhi[32K,48K) Blo[48K,64K)
// 128 rows x 128 B (64 bf16 = K64). 8 x 16B chunks/row; swizzle chunk ^= row&7.
#define STAGE_SZ 65536
#define STAGES   3
#define SMEM_BYTES (STAGES * STAGE_SZ)

// C = alpha * A @ B^T (+bias). EPI: 0=fp32, 1=hi/lo bf16, 2=hi/lo transposed [B][D][S]
template <int HAS_BIAS, int EPI>
__global__ __launch_bounds__(256, 1)
void mm_kernel(const bf16* __restrict__ Ahi, const bf16* __restrict__ Alo,
               const bf16* __restrict__ Bhi, const bf16* __restrict__ Blo,
               const float* __restrict__ bias,
               float* __restrict__ Cf, bf16* __restrict__ Chi, bf16* __restrict__ Clo,
               int M, int N, int K,
               long long sA, long long sB, long long sC, float alpha)
{
    extern __shared__ char sm[];
    const uint32_t sb = smem_u32(sm);
    const int tid  = threadIdx.x;
    const int lane = tid & 31;
    const int wid  = tid >> 5;
    const int wm   = wid >> 2;
    const int wn   = wid & 3;

    const long long aoff = blockIdx.z * sA + (long long)(blockIdx.y * 128) * K;
    const long long boff = blockIdx.z * sB + (long long)(blockIdx.x * 128) * K;

    // ---- cp.async loader: thread -> row = tid>>1, 4 consecutive 16B chunks ----
    const int lrow = tid >> 1;
    const int cg   = (tid & 1) * 4;
    const int swr  = lrow & 7;
    uint32_t wdst[4];
#pragma unroll
    for (int j = 0; j < 4; j++) wdst[j] = lrow * 128 + (((cg + j) ^ swr) << 4);
    const bf16* sAhi = Ahi + aoff + (long long)lrow * K + cg * 8;
    const bf16* sAlo = Alo + aoff + (long long)lrow * K + cg * 8;
    const bf16* sBhi = Bhi + boff + (long long)lrow * K + cg * 8;
    const bf16* sBlo = Blo + boff + (long long)lrow * K + cg * 8;

    auto load_stage = [&](int kofs, int stg) {
        const uint32_t stb = sb + stg * STAGE_SZ;
#pragma unroll
        for (int j = 0; j < 4; j++) CP16(stb + wdst[j],         sAhi + kofs + 8 * j);
#pragma unroll
        for (int j = 0; j < 4; j++) CP16(stb + 16384 + wdst[j], sAlo + kofs + 8 * j);
#pragma unroll
        for (int j = 0; j < 4; j++) CP16(stb + 32768 + wdst[j], sBhi + kofs + 8 * j);
#pragma unroll
        for (int j = 0; j < 4; j++) CP16(stb + 49152 + wdst[j], sBlo + kofs + 8 * j);
    };

    // ---- ldmatrix addressing ----
    const int g      = lane >> 3;
    const int rr     = lane & 7;
    const int rowoff = ((g & 1) << 3) + rr;   // 0..15
    const int csel   = g >> 1;                // 0..1 (k halves within 16)
    const int sw     = rowoff & 7;
    uint32_t aRowB[4], bRowB[2];
#pragma unroll
    for (int mt = 0; mt < 4; mt++) aRowB[mt] = (wm * 64 + mt * 16 + rowoff) * 128;
#pragma unroll
    for (int pr = 0; pr < 2; pr++) bRowB[pr] = (wn * 32 + pr * 16 + rowoff) * 128;

    // fragment double buffers
    uint32_t ah[2][4][4], al[2][4][4], bh[2][4][2], bl[2][4][2];

    float cacc[4][4][4];
#pragma unroll
    for (int i = 0; i < 4; i++)
#pragma unroll
        for (int j = 0; j < 4; j++)
#pragma unroll
            for (int q = 0; q < 4; q++) cacc[i][j][q] = 0.0f;

    auto ldsm_slice = [&](uint32_t stb, int s, int buf) {
        const uint32_t ck = (uint32_t)((((s << 1) + csel) ^ sw) << 4);
#pragma unroll
        for (int mt = 0; mt < 4; mt++) {
            LDSM4(ah[buf][mt], stb + aRowB[mt] + ck);
            LDSM4(al[buf][mt], stb + 16384 + aRowB[mt] + ck);
        }
#pragma unroll
        for (int pr = 0; pr < 2; pr++) {
            uint32_t t[4];
            LDSM4(t, stb + 32768 + bRowB[pr] + ck);
            bh[buf][2 * pr][0] = t[0]; bh[buf][2 * pr + 1][0] = t[1];
            bh[buf][2 * pr][1] = t[2]; bh[buf][2 * pr + 1][1] = t[3];
            LDSM4(t, stb + 49152 + bRowB[pr] + ck);
            bl[buf][2 * pr][0] = t[0]; bl[buf][2 * pr + 1][0] = t[1];
            bl[buf][2 * pr][1] = t[2]; bl[buf][2 * pr + 1][1] = t[3];
        }
    };

    auto mma_frag = [&](int buf) {
#pragma unroll
        for (int mt = 0; mt < 4; mt++)
#pragma unroll
            for (int nt = 0; nt < 4; nt++) {
                MMA(cacc[mt][nt], ah[buf][mt], bh[buf][nt]);
                MMA(cacc[mt][nt], ah[buf][mt], bl[buf][nt]);
                MMA(cacc[mt][nt], al[buf][mt], bh[buf][nt]);
            }
    };

    const int NSt = K >> 6;       // K64 stages
    load_stage(0, 0);  CP_COMMIT();
    load_stage(64, 1); CP_COMMIT();
    CP_WAIT1();
    __syncthreads();
    ldsm_slice(sb, 0, 0);

    for (int c = 0; c < NSt; c++) {
        const uint32_t stb = sb + (c % 3) * STAGE_SZ;
#pragma unroll
        for (int s = 0; s < 4; s++) {
            if (s < 3) ldsm_slice(stb, s + 1, (s + 1) & 1);
            mma_frag(s & 1);
        }
        if (c + 2 < NSt) load_stage((c + 2) << 6, (c + 2) % 3);
        CP_COMMIT();
        if (c + 1 < NSt) {
            CP_WAIT1();
            __syncthreads();
            ldsm_slice(sb + ((c + 1) % 3) * STAGE_SZ, 0, 0);
        }
    }

    // ---- epilogue ----
    const int l4 = lane >> 2;
    const int l2 = (lane & 3) * 2;
#pragma unroll
    for (int mt = 0; mt < 4; mt++) {
        const int mg = blockIdx.y * 128 + wm * 64 + mt * 16 + l4;
#pragma unroll
        for (int nt = 0; nt < 4; nt++) {
            const int n = blockIdx.x * 128 + wn * 32 + nt * 8 + l2;
            float b0 = 0.f, b1 = 0.f;
            if (HAS_BIAS) { b0 = bias[n]; b1 = bias[n + 1]; }
            float f0 = cacc[mt][nt][0] * alpha + b0;
            float f1 = cacc[mt][nt][1] * alpha + b1;
            float f2 = cacc[mt][nt][2] * alpha + b0;
            float f3 = cacc[mt][nt][3] * alpha + b1;
            if (EPI == 0) {
                float* cb = Cf + blockIdx.z * sC;
                *(float2*)&cb[(long long)mg * N + n]       = make_float2(f0, f1);
                *(float2*)&cb[(long long)(mg + 8) * N + n] = make_float2(f2, f3);
            } else if (EPI == 1) {
                uint32_t h, l;
                split2(f0, f1, h, l);
                *(uint32_t*)&Chi[blockIdx.z * sC + (long long)mg * N + n] = h;
                *(uint32_t*)&Clo[blockIdx.z * sC + (long long)mg * N + n] = l;
                split2(f2, f3, h, l);
                *(uint32_t*)&Chi[blockIdx.z * sC + (long long)(mg + 8) * N + n] = h;
                *(uint32_t*)&Clo[blockIdx.z * sC + (long long)(mg + 8) * N + n] = l;
            } else {
                const int b  = mg >> 11;
                const int s2 = mg & 2047;
                bf16* vh = Chi + (long long)b * EMBED * SEQ + s2;
                bf16* vl = Clo + (long long)b * EMBED * SEQ + s2;
                uint32_t h, l;
                split2(f0, f1, h, l);
                vh[(long long)n * SEQ]       = __ushort_as_bfloat16((unsigned short)(h & 0xFFFF));
                vh[(long long)(n + 1) * SEQ] = __ushort_as_bfloat16((unsigned short)(h >> 16));
                vl[(long long)n * SEQ]       = __ushort_as_bfloat16((unsigned short)(l & 0xFFFF));
                vl[(long long)(n + 1) * SEQ] = __ushort_as_bfloat16((unsigned short)(l >> 16));
                split2(f2, f3, h, l);
                vh[(long long)n * SEQ + 8]       = __ushort_as_bfloat16((unsigned short)(h & 0xFFFF));
                vh[(long long)(n + 1) * SEQ + 8] = __ushort_as_bfloat16((unsigned short)(h >> 16));
                vl[(long long)n * SEQ + 8]       = __ushort_as_bfloat16((unsigned short)(l & 0xFFFF));
                vl[(long long)(n + 1) * SEQ + 8] = __ushort_as_bfloat16((unsigned short)(l >> 16));
            }
        }
    }
}

// ---------------------------------------------------------------------------
__global__ __launch_bounds__(256)
void softmax_kernel(const float* __restrict__ S, bf16* __restrict__ Phi, bf16* __restrict__ Plo)
{
    const float* row = S + (long long)blockIdx.x * SEQ;
    const int t = threadIdx.x;
    const int lane = t & 31;
    const int wid  = t >> 5;

    float4 v0 = ((const float4*)row)[t];
    float4 v1 = ((const float4*)row)[t + 256];

    float m = fmaxf(fmaxf(fmaxf(v0.x, v0.y), fmaxf(v0.z, v0.w)),
                    fmaxf(fmaxf(v1.x, v1.y), fmaxf(v1.z, v1.w)));
#pragma unroll
    for (int o = 16; o > 0; o >>= 1)
        m = fmaxf(m, __shfl_xor_sync(0xFFFFFFFFu, m, o));

    __shared__ float red[8];
    if (lane == 0) red[wid] = m;
    __syncthreads();
    float M = red[0];
#pragma unroll
    for (int i = 1; i < 8; i++) M = fmaxf(M, red[i]);
    __syncthreads();

    v0.x = __expf(v0.x - M); v0.y = __expf(v0.y - M);
    v0.z = __expf(v0.z - M); v0.w = __expf(v0.w - M);
    v1.x = __expf(v1.x - M); v1.y = __expf(v1.y - M);
    v1.z = __expf(v1.z - M); v1.w = __expf(v1.w - M);

    float s = (v0.x + v0.y + v0.z + v0.w) + (v1.x + v1.y + v1.z + v1.w);
#pragma unroll
    for (int o = 16; o > 0; o >>= 1)
        s += __shfl_xor_sync(0xFFFFFFFFu, s, o);
    if (lane == 0) red[wid] = s;
    __syncthreads();
    float Ssum = 0.0f;
#pragma unroll
    for (int i = 0; i < 8; i++) Ssum += red[i];

    const float inv = 1.0f / Ssum;
    v0.x *= inv; v0.y *= inv; v0.z *= inv; v0.w *= inv;
    v1.x *= inv; v1.y *= inv; v1.z *= inv; v1.w *= inv;

    uint2* ph = (uint2*)(Phi + (long long)blockIdx.x * SEQ);
    uint2* pl = (uint2*)(Plo + (long long)blockIdx.x * SEQ);
    uint32_t h01, l01, h23, l23;
    split2(v0.x, v0.y, h01, l01); split2(v0.z, v0.w, h23, l23);
    ph[t] = make_uint2(h01, h23); pl[t] = make_uint2(l01, l23);
    split2(v1.x, v1.y, h01, l01); split2(v1.z, v1.w, h23, l23);
    ph[t + 256] = make_uint2(h01, h23); pl[t + 256] = make_uint2(l01, l23);
}

__global__ __launch_bounds__(256)
void cvt_kernel(const float* __restrict__ src, bf16* __restrict__ hi, bf16* __restrict__ lo, int n4)
{
    int i = blockIdx.x * blockDim.x + threadIdx.x;
    if (i >= n4) return;
    float4 v = ((const float4*)src)[i];
    uint32_t h01, l01, h23, l23;
    split2(v.x, v.y, h01, l01);
    split2(v.z, v.w, h23, l23);
    ((uint2*)hi)[i] = make_uint2(h01, h23);
    ((uint2*)lo)[i] = make_uint2(l01, l23);
}

extern "C" void kernel_launch(void* const* d_in, const int* in_sizes, int n_in,
                              void* d_out, int out_size)
{
    const float* target = (const float*)d_in[0];
    const float* source = (const float*)d_in[1];
    const float* Wq     = (const float*)d_in[2];
    const float* bq     = (const float*)d_in[3];
    const float* Wk     = (const float*)d_in[4];
    const float* bk     = (const float*)d_in[5];
    const float* Wv     = (const float*)d_in[6];
    const float* bv     = (const float*)d_in[7];
    const float* Wo     = (const float*)d_in[8];
    const float* bo     = (const float*)d_in[9];
    float* out = (float*)d_out;

    float* Sc;
    cudaGetSymbolAddress((void**)&Sc, g_Sc);
    bf16 *Thi,*Tlo,*Shi,*Slo,*Wqh,*Wql,*Wkh,*Wkl,*Wvh,*Wvl,*Woh,*Wol;
    bf16 *Qhi,*Qlo,*Khi,*Klo,*Vth,*Vtl,*Phi,*Plo,*Chi,*Clo;
    cudaGetSymbolAddress((void**)&Thi, g_Thi);  cudaGetSymbolAddress((void**)&Tlo, g_Tlo);
    cudaGetSymbolAddress((void**)&Shi, g_Shi);  cudaGetSymbolAddress((void**)&Slo, g_Slo);
    cudaGetSymbolAddress((void**)&Wqh, g_Wqhi); cudaGetSymbolAddress((void**)&Wql, g_Wqlo);
    cudaGetSymbolAddress((void**)&Wkh, g_Wkhi); cudaGetSymbolAddress((void**)&Wkl, g_Wklo);
    cudaGetSymbolAddress((void**)&Wvh, g_Wvhi); cudaGetSymbolAddress((void**)&Wvl, g_Wvlo);
    cudaGetSymbolAddress((void**)&Woh, g_Wohi); cudaGetSymbolAddress((void**)&Wol, g_Wolo);
    cudaGetSymbolAddress((void**)&Qhi, g_Qhi);  cudaGetSymbolAddress((void**)&Qlo, g_Qlo);
    cudaGetSymbolAddress((void**)&Khi, g_Khi);  cudaGetSymbolAddress((void**)&Klo, g_Klo);
    cudaGetSymbolAddress((void**)&Vth, g_Vthi); cudaGetSymbolAddress((void**)&Vtl, g_Vtlo);
    cudaGetSymbolAddress((void**)&Phi, g_Phi);  cudaGetSymbolAddress((void**)&Plo, g_Plo);
    cudaGetSymbolAddress((void**)&Chi, g_Chi);  cudaGetSymbolAddress((void**)&Clo, g_Clo);

    cudaFuncSetAttribute(mm_kernel<1, 1>, cudaFuncAttributeMaxDynamicSharedMemorySize, SMEM_BYTES);
    cudaFuncSetAttribute(mm_kernel<1, 2>, cudaFuncAttributeMaxDynamicSharedMemorySize, SMEM_BYTES);
    cudaFuncSetAttribute(mm_kernel<0, 0>, cudaFuncAttributeMaxDynamicSharedMemorySize, SMEM_BYTES);
    cudaFuncSetAttribute(mm_kernel<0, 1>, cudaFuncAttributeMaxDynamicSharedMemorySize, SMEM_BYTES);
    cudaFuncSetAttribute(mm_kernel<1, 0>, cudaFuncAttributeMaxDynamicSharedMemorySize, SMEM_BYTES);

    const int nIn  = MTOT * EMBED / 4;
    const int nW   = EMBED * EMBED / 4;
    cvt_kernel<<<(nIn + 255) / 256, 256>>>(target, Thi, Tlo, nIn);
    cvt_kernel<<<(nIn + 255) / 256, 256>>>(source, Shi, Slo, nIn);
    cvt_kernel<<<(nW + 255) / 256, 256>>>(Wq, Wqh, Wql, nW);
    cvt_kernel<<<(nW + 255) / 256, 256>>>(Wk, Wkh, Wkl, nW);
    cvt_kernel<<<(nW + 255) / 256, 256>>>(Wv, Wvh, Wvl, nW);
    cvt_kernel<<<(nW + 255) / 256, 256>>>(Wo, Woh, Wol, nW);

    dim3 gProj(EMBED / 128, MTOT / 128, 1);
    mm_kernel<1, 1><<<gProj, 256, SMEM_BYTES>>>(Thi, Tlo, Wqh, Wql, bq, nullptr, Qhi, Qlo,
                                                MTOT, EMBED, EMBED, 0, 0, 0, 1.0f);
    mm_kernel<1, 1><<<gProj, 256, SMEM_BYTES>>>(Shi, Slo, Wkh, Wkl, bk, nullptr, Khi, Klo,
                                                MTOT, EMBED, EMBED, 0, 0, 0, 1.0f);
    mm_kernel<1, 2><<<gProj, 256, SMEM_BYTES>>>(Shi, Slo, Wvh, Wvl, bv, nullptr, Vth, Vtl,
                                                MTOT, EMBED, EMBED, 0, 0, 0, 1.0f);

    dim3 gScore(SEQ / 128, SEQ / 128, BATCH);
    mm_kernel<0, 0><<<gScore, 256, SMEM_BYTES>>>(Qhi, Qlo, Khi, Klo, nullptr, Sc, nullptr, nullptr,
                                                 SEQ, SEQ, EMBED,
                                                 (long long)SEQ * EMBED, (long long)SEQ * EMBED,
                                                 (long long)SEQ * SEQ, 0.03125f);

    softmax_kernel<<<BATCH * SEQ, 256>>>(Sc, Phi, Plo);

    dim3 gAV(EMBED / 128, SEQ / 128, BATCH);
    mm_kernel<0, 1><<<gAV, 256, SMEM_BYTES>>>(Phi, Plo, Vth, Vtl, nullptr, nullptr, Chi, Clo,
                                              SEQ, EMBED, SEQ,
                                              (long long)SEQ * SEQ, (long long)EMBED * SEQ,
                                              (long long)SEQ * EMBED, 1.0f);

    mm_kernel<1, 0><<<gProj, 256, SMEM_BYTES>>>(Chi, Clo, Woh, Wol, bo, out, nullptr, nullptr,
                                                MTOT, EMBED, EMBED, 0, 0, 0, 1.0f);
}

// round 7
// speedup vs baseline: 2.3259x; 1.1409x over previous
#include <cuda_runtime.h>
#include <cuda_bf16.h>
#include <cstdint>
#include <math.h>

// ---------------------------------------------------------------------------
// CrossAttention B=8, T=S=2048, D=1024 (single head).
// R5: split-bf16 3-product fp32 emu on mma.sync m16n8k16.
// 128x128 CTA tile, 512 threads (16 warps, 4/SMSP), warp tile 32x32,
// product-major MMA order, K32 smem stages x4, cp.async depth-3 pipeline.
// ---------------------------------------------------------------------------

#define EMBED 1024
#define BATCH 8
#define SEQ   2048
#define MTOT  (BATCH * SEQ)

typedef __nv_bfloat16 bf16;

__device__ float g_Sc[(long long)BATCH * SEQ * SEQ];
__device__ bf16 g_Thi[MTOT * EMBED], g_Tlo[MTOT * EMBED];
__device__ bf16 g_Shi[MTOT * EMBED], g_Slo[MTOT * EMBED];
__device__ bf16 g_Wqhi[EMBED * EMBED], g_Wqlo[EMBED * EMBED];
__device__ bf16 g_Wkhi[EMBED * EMBED], g_Wklo[EMBED * EMBED];
__device__ bf16 g_Wvhi[EMBED * EMBED], g_Wvlo[EMBED * EMBED];
__device__ bf16 g_Wohi[EMBED * EMBED], g_Wolo[EMBED * EMBED];
__device__ bf16 g_Qhi[MTOT * EMBED],  g_Qlo[MTOT * EMBED];
__device__ bf16 g_Khi[MTOT * EMBED],  g_Klo[MTOT * EMBED];
__device__ bf16 g_Vthi[MTOT * EMBED], g_Vtlo[MTOT * EMBED];   // [B][D][S]
__device__ bf16 g_Phi[(long long)BATCH * SEQ * SEQ], g_Plo[(long long)BATCH * SEQ * SEQ];
__device__ bf16 g_Chi[MTOT * EMBED],  g_Clo[MTOT * EMBED];

__device__ __forceinline__ uint32_t smem_u32(const void* p) {
    uint32_t a;
    asm("{ .reg .u64 t; cvta.to.shared.u64 t, %1; cvt.u32.u64 %0, t; }" : "=r"(a) : "l"(p));
    return a;
}

#define LDSM4(r, addr) \
    asm volatile("ldmatrix.sync.aligned.m8n8.x4.shared.b16 {%0,%1,%2,%3}, [%4];" \
        : "=r"((r)[0]), "=r"((r)[1]), "=r"((r)[2]), "=r"((r)[3]) : "r"(addr))

#define MMA(d, a, b) \
    asm volatile("mma.sync.aligned.m16n8k16.row.col.f32.bf16.bf16.f32 " \
        "{%0,%1,%2,%3}, {%4,%5,%6,%7}, {%8,%9}, {%0,%1,%2,%3};" \
        : "+f"((d)[0]), "+f"((d)[1]), "+f"((d)[2]), "+f"((d)[3]) \
        : "r"((a)[0]), "r"((a)[1]), "r"((a)[2]), "r"((a)[3]), "r"((b)[0]), "r"((b)[1]))

#define CP16(dst, src) \
    asm volatile("cp.async.cg.shared.global [%0], [%1], 16;" :: "r"(dst), "l"(src))
#define CP_COMMIT() asm volatile("cp.async.commit_group;" ::: "memory")
#define CP_WAIT2()  asm volatile("cp.async.wait_group 2;" ::: "memory")

__device__ __forceinline__ void split2(float f0, float f1, uint32_t& hi, uint32_t& lo) {
    asm("cvt.rn.bf16x2.f32 %0, %1, %2;" : "=r"(hi) : "f"(f1), "f"(f0));
    float r0 = f0 - __uint_as_float(hi << 16);
    float r1 = f1 - __uint_as_float(hi & 0xFFFF0000u);
    asm("cvt.rn.bf16x2.f32 %0, %1, %2;" : "=r"(lo) : "f"(r1), "f"(r0));
}

// Stage (32 KB): Ahi[0,8K) Alo[8K,16K) Bhi[16K,24K) Blo[24K,32K)
// Tile: 128 rows x 64B (32 bf16). 4 chunks of 16B/row; swizzle chunk ^= (row>>1)&3
#define STAGE_SZ 32768
#define STAGES   4
#define SMEM_BYTES (STAGES * STAGE_SZ)

// C = alpha * A @ B^T (+bias). EPI: 0=fp32, 1=hi/lo bf16, 2=hi/lo transposed [B][D][S]
template <int HAS_BIAS, int EPI>
__global__ __launch_bounds__(512, 1)
void mm_kernel(const bf16* __restrict__ Ahi, const bf16* __restrict__ Alo,
               const bf16* __restrict__ Bhi, const bf16* __restrict__ Blo,
               const float* __restrict__ bias,
               float* __restrict__ Cf, bf16* __restrict__ Chi, bf16* __restrict__ Clo,
               int M, int N, int K,
               long long sA, long long sB, long long sC, float alpha)
{
    extern __shared__ char sm[];
    const uint32_t sb = smem_u32(sm);
    const int tid  = threadIdx.x;
    const int lane = tid & 31;
    const int wid  = tid >> 5;
    const int wm   = wid >> 2;   // 0..3 (32 rows each)
    const int wn   = wid & 3;    // 0..3 (32 cols each)

    const long long aoff = blockIdx.z * sA + (long long)(blockIdx.y * 128) * K;
    const long long boff = blockIdx.z * sB + (long long)(blockIdx.x * 128) * K;

    // ---- cp.async loader: tid -> row = tid>>2, chunk = tid&3 (1 per tile) ----
    const int lrow = tid >> 2;
    const int c0   = tid & 3;
    const uint32_t d0 = lrow * 64 + ((c0 ^ ((lrow >> 1) & 3)) << 4);
    const bf16* pAhi = Ahi + aoff + (long long)lrow * K + c0 * 8;
    const bf16* pAlo = Alo + aoff + (long long)lrow * K + c0 * 8;
    const bf16* pBhi = Bhi + boff + (long long)lrow * K + c0 * 8;
    const bf16* pBlo = Blo + boff + (long long)lrow * K + c0 * 8;

    auto load_stage = [&](int kofs, int st) {
        const uint32_t stb = sb + st * STAGE_SZ;
        CP16(stb + d0,         pAhi + kofs);
        CP16(stb + 8192  + d0, pAlo + kofs);
        CP16(stb + 16384 + d0, pBhi + kofs);
        CP16(stb + 24576 + d0, pBlo + kofs);
    };

    // ---- ldmatrix addressing ----
    const int g      = lane >> 3;
    const int rr     = lane & 7;
    const int rowoff = ((g & 1) << 3) + rr;   // 0..15
    const int csel   = g >> 1;                // 0..1
    const int sw     = (rowoff >> 1) & 3;
    uint32_t aRowB[2], bRowB[2];
#pragma unroll
    for (int mt = 0; mt < 2; mt++) aRowB[mt] = (wm * 32 + mt * 16 + rowoff) * 64;
#pragma unroll
    for (int pr = 0; pr < 2; pr++) bRowB[pr] = (wn * 32 + pr * 16 + rowoff) * 64;

    uint32_t ah[2][4], al[2][4], bh[4][2], bl[4][2];
    float cacc[2][4][4];
#pragma unroll
    for (int i = 0; i < 2; i++)
#pragma unroll
        for (int j = 0; j < 4; j++)
#pragma unroll
            for (int q = 0; q < 4; q++) cacc[i][j][q] = 0.0f;

    auto ldsm_slice = [&](uint32_t stb, int s) {
        const uint32_t ck = (uint32_t)((((s << 1) + csel) ^ sw) << 4);
#pragma unroll
        for (int mt = 0; mt < 2; mt++) {
            LDSM4(ah[mt], stb + aRowB[mt] + ck);
            LDSM4(al[mt], stb + 8192 + aRowB[mt] + ck);
        }
#pragma unroll
        for (int pr = 0; pr < 2; pr++) {
            uint32_t t[4];
            LDSM4(t, stb + 16384 + bRowB[pr] + ck);
            bh[2 * pr][0] = t[0]; bh[2 * pr + 1][0] = t[1];
            bh[2 * pr][1] = t[2]; bh[2 * pr + 1][1] = t[3];
            LDSM4(t, stb + 24576 + bRowB[pr] + ck);
            bl[2 * pr][0] = t[0]; bl[2 * pr + 1][0] = t[1];
            bl[2 * pr][1] = t[2]; bl[2 * pr + 1][1] = t[3];
        }
    };

    // product-major: 8 independent accumulators between same-acc reuse
    auto mma_all = [&]() {
#pragma unroll
        for (int mt = 0; mt < 2; mt++)
#pragma unroll
            for (int nt = 0; nt < 4; nt++) MMA(cacc[mt][nt], ah[mt], bh[nt]);
#pragma unroll
        for (int mt = 0; mt < 2; mt++)
#pragma unroll
            for (int nt = 0; nt < 4; nt++) MMA(cacc[mt][nt], ah[mt], bl[nt]);
#pragma unroll
        for (int mt = 0; mt < 2; mt++)
#pragma unroll
            for (int nt = 0; nt < 4; nt++) MMA(cacc[mt][nt], al[mt], bh[nt]);
    };

    const int NSt = K >> 5;
    load_stage(0, 0);  CP_COMMIT();
    load_stage(32, 1); CP_COMMIT();
    load_stage(64, 2); CP_COMMIT();

    for (int c = 0; c < NSt; c++) {
        CP_WAIT2();
        __syncthreads();
        if (c + 3 < NSt) load_stage((c + 3) << 5, (c + 3) & 3);
        CP_COMMIT();
        const uint32_t stb = sb + (c & 3) * STAGE_SZ;
#pragma unroll
        for (int s = 0; s < 2; s++) {
            ldsm_slice(stb, s);
            mma_all();
        }
    }

    // ---- epilogue ----
    const int l4 = lane >> 2;
    const int l2 = (lane & 3) * 2;
#pragma unroll
    for (int mt = 0; mt < 2; mt++) {
        const int mg = blockIdx.y * 128 + wm * 32 + mt * 16 + l4;
#pragma unroll
        for (int nt = 0; nt < 4; nt++) {
            const int n = blockIdx.x * 128 + wn * 32 + nt * 8 + l2;
            float b0 = 0.f, b1 = 0.f;
            if (HAS_BIAS) { b0 = bias[n]; b1 = bias[n + 1]; }
            float f0 = cacc[mt][nt][0] * alpha + b0;
            float f1 = cacc[mt][nt][1] * alpha + b1;
            float f2 = cacc[mt][nt][2] * alpha + b0;
            float f3 = cacc[mt][nt][3] * alpha + b1;
            if (EPI == 0) {
                float* cb = Cf + blockIdx.z * sC;
                *(float2*)&cb[(long long)mg * N + n]       = make_float2(f0, f1);
                *(float2*)&cb[(long long)(mg + 8) * N + n] = make_float2(f2, f3);
            } else if (EPI == 1) {
                uint32_t h, l;
                split2(f0, f1, h, l);
                *(uint32_t*)&Chi[blockIdx.z * sC + (long long)mg * N + n] = h;
                *(uint32_t*)&Clo[blockIdx.z * sC + (long long)mg * N + n] = l;
                split2(f2, f3, h, l);
                *(uint32_t*)&Chi[blockIdx.z * sC + (long long)(mg + 8) * N + n] = h;
                *(uint32_t*)&Clo[blockIdx.z * sC + (long long)(mg + 8) * N + n] = l;
            } else {
                const int b  = mg >> 11;
                const int s2 = mg & 2047;
                bf16* vh = Chi + (long long)b * EMBED * SEQ + s2;
                bf16* vl = Clo + (long long)b * EMBED * SEQ + s2;
                uint32_t h, l;
                split2(f0, f1, h, l);
                vh[(long long)n * SEQ]       = __ushort_as_bfloat16((unsigned short)(h & 0xFFFF));
                vh[(long long)(n + 1) * SEQ] = __ushort_as_bfloat16((unsigned short)(h >> 16));
                vl[(long long)n * SEQ]       = __ushort_as_bfloat16((unsigned short)(l & 0xFFFF));
                vl[(long long)(n + 1) * SEQ] = __ushort_as_bfloat16((unsigned short)(l >> 16));
                split2(f2, f3, h, l);
                vh[(long long)n * SEQ + 8]       = __ushort_as_bfloat16((unsigned short)(h & 0xFFFF));
                vh[(long long)(n + 1) * SEQ + 8] = __ushort_as_bfloat16((unsigned short)(h >> 16));
                vl[(long long)n * SEQ + 8]       = __ushort_as_bfloat16((unsigned short)(l & 0xFFFF));
                vl[(long long)(n + 1) * SEQ + 8] = __ushort_as_bfloat16((unsigned short)(l >> 16));
            }
        }
    }
}

// ---------------------------------------------------------------------------
__global__ __launch_bounds__(256)
void softmax_kernel(const float* __restrict__ S, bf16* __restrict__ Phi, bf16* __restrict__ Plo)
{
    const float* row = S + (long long)blockIdx.x * SEQ;
    const int t = threadIdx.x;
    const int lane = t & 31;
    const int wid  = t >> 5;

    float4 v0 = ((const float4*)row)[t];
    float4 v1 = ((const float4*)row)[t + 256];

    float m = fmaxf(fmaxf(fmaxf(v0.x, v0.y), fmaxf(v0.z, v0.w)),
                    fmaxf(fmaxf(v1.x, v1.y), fmaxf(v1.z, v1.w)));
#pragma unroll
    for (int o = 16; o > 0; o >>= 1)
        m = fmaxf(m, __shfl_xor_sync(0xFFFFFFFFu, m, o));

    __shared__ float red[8];
    if (lane == 0) red[wid] = m;
    __syncthreads();
    float M = red[0];
#pragma unroll
    for (int i = 1; i < 8; i++) M = fmaxf(M, red[i]);
    __syncthreads();

    v0.x = __expf(v0.x - M); v0.y = __expf(v0.y - M);
    v0.z = __expf(v0.z - M); v0.w = __expf(v0.w - M);
    v1.x = __expf(v1.x - M); v1.y = __expf(v1.y - M);
    v1.z = __expf(v1.z - M); v1.w = __expf(v1.w - M);

    float s = (v0.x + v0.y + v0.z + v0.w) + (v1.x + v1.y + v1.z + v1.w);
#pragma unroll
    for (int o = 16; o > 0; o >>= 1)
        s += __shfl_xor_sync(0xFFFFFFFFu, s, o);
    if (lane == 0) red[wid] = s;
    __syncthreads();
    float Ssum = 0.0f;
#pragma unroll
    for (int i = 0; i < 8; i++) Ssum += red[i];

    const float inv = 1.0f / Ssum;
    v0.x *= inv; v0.y *= inv; v0.z *= inv; v0.w *= inv;
    v1.x *= inv; v1.y *= inv; v1.z *= inv; v1.w *= inv;

    uint2* ph = (uint2*)(Phi + (long long)blockIdx.x * SEQ);
    uint2* pl = (uint2*)(Plo + (long long)blockIdx.x * SEQ);
    uint32_t h01, l01, h23, l23;
    split2(v0.x, v0.y, h01, l01); split2(v0.z, v0.w, h23, l23);
    ph[t] = make_uint2(h01, h23); pl[t] = make_uint2(l01, l23);
    split2(v1.x, v1.y, h01, l01); split2(v1.z, v1.w, h23, l23);
    ph[t + 256] = make_uint2(h01, h23); pl[t + 256] = make_uint2(l01, l23);
}

__global__ __launch_bounds__(256)
void cvt_kernel(const float* __restrict__ src, bf16* __restrict__ hi, bf16* __restrict__ lo, int n4)
{
    int i = blockIdx.x * blockDim.x + threadIdx.x;
    if (i >= n4) return;
    float4 v = ((const float4*)src)[i];
    uint32_t h01, l01, h23, l23;
    split2(v.x, v.y, h01, l01);
    split2(v.z, v.w, h23, l23);
    ((uint2*)hi)[i] = make_uint2(h01, h23);
    ((uint2*)lo)[i] = make_uint2(l01, l23);
}

extern "C" void kernel_launch(void* const* d_in, const int* in_sizes, int n_in,
                              void* d_out, int out_size)
{
    const float* target = (const float*)d_in[0];
    const float* source = (const float*)d_in[1];
    const float* Wq     = (const float*)d_in[2];
    const float* bq     = (const float*)d_in[3];
    const float* Wk     = (const float*)d_in[4];
    const float* bk     = (const float*)d_in[5];
    const float* Wv     = (const float*)d_in[6];
    const float* bv     = (const float*)d_in[7];
    const float* Wo     = (const float*)d_in[8];
    const float* bo     = (const float*)d_in[9];
    float* out = (float*)d_out;

    float* Sc;
    cudaGetSymbolAddress((void**)&Sc, g_Sc);
    bf16 *Thi,*Tlo,*Shi,*Slo,*Wqh,*Wql,*Wkh,*Wkl,*Wvh,*Wvl,*Woh,*Wol;
    bf16 *Qhi,*Qlo,*Khi,*Klo,*Vth,*Vtl,*Phi,*Plo,*Chi,*Clo;
    cudaGetSymbolAddress((void**)&Thi, g_Thi);  cudaGetSymbolAddress((void**)&Tlo, g_Tlo);
    cudaGetSymbolAddress((void**)&Shi, g_Shi);  cudaGetSymbolAddress((void**)&Slo, g_Slo);
    cudaGetSymbolAddress((void**)&Wqh, g_Wqhi); cudaGetSymbolAddress((void**)&Wql, g_Wqlo);
    cudaGetSymbolAddress((void**)&Wkh, g_Wkhi); cudaGetSymbolAddress((void**)&Wkl, g_Wklo);
    cudaGetSymbolAddress((void**)&Wvh, g_Wvhi); cudaGetSymbolAddress((void**)&Wvl, g_Wvlo);
    cudaGetSymbolAddress((void**)&Woh, g_Wohi); cudaGetSymbolAddress((void**)&Wol, g_Wolo);
    cudaGetSymbolAddress((void**)&Qhi, g_Qhi);  cudaGetSymbolAddress((void**)&Qlo, g_Qlo);
    cudaGetSymbolAddress((void**)&Khi, g_Khi);  cudaGetSymbolAddress((void**)&Klo, g_Klo);
    cudaGetSymbolAddress((void**)&Vth, g_Vthi); cudaGetSymbolAddress((void**)&Vtl, g_Vtlo);
    cudaGetSymbolAddress((void**)&Phi, g_Phi);  cudaGetSymbolAddress((void**)&Plo, g_Plo);
    cudaGetSymbolAddress((void**)&Chi, g_Chi);  cudaGetSymbolAddress((void**)&Clo, g_Clo);

    cudaFuncSetAttribute(mm_kernel<1, 1>, cudaFuncAttributeMaxDynamicSharedMemorySize, SMEM_BYTES);
    cudaFuncSetAttribute(mm_kernel<1, 2>, cudaFuncAttributeMaxDynamicSharedMemorySize, SMEM_BYTES);
    cudaFuncSetAttribute(mm_kernel<0, 0>, cudaFuncAttributeMaxDynamicSharedMemorySize, SMEM_BYTES);
    cudaFuncSetAttribute(mm_kernel<0, 1>, cudaFuncAttributeMaxDynamicSharedMemorySize, SMEM_BYTES);
    cudaFuncSetAttribute(mm_kernel<1, 0>, cudaFuncAttributeMaxDynamicSharedMemorySize, SMEM_BYTES);

    const int nIn  = MTOT * EMBED / 4;
    const int nW   = EMBED * EMBED / 4;
    cvt_kernel<<<(nIn + 255) / 256, 256>>>(target, Thi, Tlo, nIn);
    cvt_kernel<<<(nIn + 255) / 256, 256>>>(source, Shi, Slo, nIn);
    cvt_kernel<<<(nW + 255) / 256, 256>>>(Wq, Wqh, Wql, nW);
    cvt_kernel<<<(nW + 255) / 256, 256>>>(Wk, Wkh, Wkl, nW);
    cvt_kernel<<<(nW + 255) / 256, 256>>>(Wv, Wvh, Wvl, nW);
    cvt_kernel<<<(nW + 255) / 256, 256>>>(Wo, Woh, Wol, nW);

    dim3 gProj(EMBED / 128, MTOT / 128, 1);
    mm_kernel<1, 1><<<gProj, 512, SMEM_BYTES>>>(Thi, Tlo, Wqh, Wql, bq, nullptr, Qhi, Qlo,
                                                MTOT, EMBED, EMBED, 0, 0, 0, 1.0f);
    mm_kernel<1, 1><<<gProj, 512, SMEM_BYTES>>>(Shi, Slo, Wkh, Wkl, bk, nullptr, Khi, Klo,
                                                MTOT, EMBED, EMBED, 0, 0, 0, 1.0f);
    mm_kernel<1, 2><<<gProj, 512, SMEM_BYTES>>>(Shi, Slo, Wvh, Wvl, bv, nullptr, Vth, Vtl,
                                                MTOT, EMBED, EMBED, 0, 0, 0, 1.0f);

    dim3 gScore(SEQ / 128, SEQ / 128, BATCH);
    mm_kernel<0, 0><<<gScore, 512, SMEM_BYTES>>>(Qhi, Qlo, Khi, Klo, nullptr, Sc, nullptr, nullptr,
                                                 SEQ, SEQ, EMBED,
                                                 (long long)SEQ * EMBED, (long long)SEQ * EMBED,
                                                 (long long)SEQ * SEQ, 0.03125f);

    softmax_kernel<<<BATCH * SEQ, 256>>>(Sc, Phi, Plo);

    dim3 gAV(EMBED / 128, SEQ / 128, BATCH);
    mm_kernel<0, 1><<<gAV, 512, SMEM_BYTES>>>(Phi, Plo, Vth, Vtl, nullptr, nullptr, Chi, Clo,
                                              SEQ, EMBED, SEQ,
                                              (long long)SEQ * SEQ, (long long)EMBED * SEQ,
                                              (long long)SEQ * EMBED, 1.0f);

    mm_kernel<1, 0><<<gProj, 512, SMEM_BYTES>>>(Chi, Clo, Woh, Wol, bo, out, nullptr, nullptr,
                                                MTOT, EMBED, EMBED, 0, 0, 0, 1.0f);
}

// round 8
// speedup vs baseline: 2.5802x; 1.1094x over previous
#include <cuda_runtime.h>
#include <cuda_bf16.h>
#include <cstdint>
#include <math.h>

// ---------------------------------------------------------------------------
// CrossAttention B=8, T=S=2048, D=1024 (single head).
// R7: split-bf16 3-product fp32 emu on mma.sync m16n8k16.
// 128x128 CTA tile, 512 threads (4 warps/SMSP), warp tile 32x32, product-major
// MMA order, K64 smem stages x3, fragment ping-pong across k-slices.
// ---------------------------------------------------------------------------

#define EMBED 1024
#define BATCH 8
#define SEQ   2048
#define MTOT  (BATCH * SEQ)

typedef __nv_bfloat16 bf16;

__device__ float g_Sc[(long long)BATCH * SEQ * SEQ];
__device__ bf16 g_Thi[MTOT * EMBED], g_Tlo[MTOT * EMBED];
__device__ bf16 g_Shi[MTOT * EMBED], g_Slo[MTOT * EMBED];
__device__ bf16 g_Wqhi[EMBED * EMBED], g_Wqlo[EMBED * EMBED];
__device__ bf16 g_Wkhi[EMBED * EMBED], g_Wklo[EMBED * EMBED];
__device__ bf16 g_Wvhi[EMBED * EMBED], g_Wvlo[EMBED * EMBED];
__device__ bf16 g_Wohi[EMBED * EMBED], g_Wolo[EMBED * EMBED];
__device__ bf16 g_Qhi[MTOT * EMBED],  g_Qlo[MTOT * EMBED];
__device__ bf16 g_Khi[MTOT * EMBED],  g_Klo[MTOT * EMBED];
__device__ bf16 g_Vthi[MTOT * EMBED], g_Vtlo[MTOT * EMBED];   // [B][D][S]
__device__ bf16 g_Phi[(long long)BATCH * SEQ * SEQ], g_Plo[(long long)BATCH * SEQ * SEQ];
__device__ bf16 g_Chi[MTOT * EMBED],  g_Clo[MTOT * EMBED];

__device__ __forceinline__ uint32_t smem_u32(const void* p) {
    uint32_t a;
    asm("{ .reg .u64 t; cvta.to.shared.u64 t, %1; cvt.u32.u64 %0, t; }" : "=r"(a) : "l"(p));
    return a;
}

#define LDSM4(r, addr) \
    asm volatile("ldmatrix.sync.aligned.m8n8.x4.shared.b16 {%0,%1,%2,%3}, [%4];" \
        : "=r"((r)[0]), "=r"((r)[1]), "=r"((r)[2]), "=r"((r)[3]) : "r"(addr))

#define MMA(d, a, b) \
    asm volatile("mma.sync.aligned.m16n8k16.row.col.f32.bf16.bf16.f32 " \
        "{%0,%1,%2,%3}, {%4,%5,%6,%7}, {%8,%9}, {%0,%1,%2,%3};" \
        : "+f"((d)[0]), "+f"((d)[1]), "+f"((d)[2]), "+f"((d)[3]) \
        : "r"((a)[0]), "r"((a)[1]), "r"((a)[2]), "r"((a)[3]), "r"((b)[0]), "r"((b)[1]))

#define CP16(dst, src) \
    asm volatile("cp.async.cg.shared.global [%0], [%1], 16;" :: "r"(dst), "l"(src))
#define CP_COMMIT() asm volatile("cp.async.commit_group;" ::: "memory")
#define CP_WAIT1()  asm volatile("cp.async.wait_group 1;" ::: "memory")

__device__ __forceinline__ void split2(float f0, float f1, uint32_t& hi, uint32_t& lo) {
    asm("cvt.rn.bf16x2.f32 %0, %1, %2;" : "=r"(hi) : "f"(f1), "f"(f0));
    float r0 = f0 - __uint_as_float(hi << 16);
    float r1 = f1 - __uint_as_float(hi & 0xFFFF0000u);
    asm("cvt.rn.bf16x2.f32 %0, %1, %2;" : "=r"(lo) : "f"(r1), "f"(r0));
}

// Stage (64 KB): Ahi[0,16K) Alo[16K,32K) Bhi[32K,48K) Blo[48K,64K)
// 128 rows x 128B (64 bf16, K64). 8 chunks of 16B/row; swizzle chunk ^= row&7.
#define STAGE_SZ 65536
#define STAGES   3
#define SMEM_BYTES (STAGES * STAGE_SZ)

// C = alpha * A @ B^T (+bias). EPI: 0=fp32, 1=hi/lo bf16, 2=hi/lo transposed [B][D][S]
template <int HAS_BIAS, int EPI>
__global__ __launch_bounds__(512, 1)
void mm_kernel(const bf16* __restrict__ Ahi, const bf16* __restrict__ Alo,
               const bf16* __restrict__ Bhi, const bf16* __restrict__ Blo,
               const float* __restrict__ bias,
               float* __restrict__ Cf, bf16* __restrict__ Chi, bf16* __restrict__ Clo,
               int M, int N, int K,
               long long sA, long long sB, long long sC, float alpha)
{
    extern __shared__ char sm[];
    const uint32_t sb = smem_u32(sm);
    const int tid  = threadIdx.x;
    const int lane = tid & 31;
    const int wid  = tid >> 5;
    const int wm   = wid >> 2;   // 0..3 (32 rows)
    const int wn   = wid & 3;    // 0..3 (32 cols)

    const long long aoff = blockIdx.z * sA + (long long)(blockIdx.y * 128) * K;
    const long long boff = blockIdx.z * sB + (long long)(blockIdx.x * 128) * K;

    // ---- loader: tid -> row = tid>>2, chunks {cg, cg+1} of 8 per row ----
    const int lrow = tid >> 2;
    const int cg   = (tid & 3) * 2;
    const int swr  = lrow & 7;
    const uint32_t d0 = lrow * 128 + ((cg ^ swr) << 4);
    const uint32_t d1 = lrow * 128 + (((cg + 1) ^ swr) << 4);
    const bf16* pAhi = Ahi + aoff + (long long)lrow * K + cg * 8;
    const bf16* pAlo = Alo + aoff + (long long)lrow * K + cg * 8;
    const bf16* pBhi = Bhi + boff + (long long)lrow * K + cg * 8;
    const bf16* pBlo = Blo + boff + (long long)lrow * K + cg * 8;

    auto load_stage = [&](int kofs, int st) {
        const uint32_t stb = sb + st * STAGE_SZ;
        CP16(stb + d0,         pAhi + kofs);
        CP16(stb + d1,         pAhi + kofs + 8);
        CP16(stb + 16384 + d0, pAlo + kofs);
        CP16(stb + 16384 + d1, pAlo + kofs + 8);
        CP16(stb + 32768 + d0, pBhi + kofs);
        CP16(stb + 32768 + d1, pBhi + kofs + 8);
        CP16(stb + 49152 + d0, pBlo + kofs);
        CP16(stb + 49152 + d1, pBlo + kofs + 8);
    };

    // ---- ldmatrix addressing ----
    const int g      = lane >> 3;
    const int rr     = lane & 7;
    const int rowoff = ((g & 1) << 3) + rr;   // 0..15
    const int csel   = g >> 1;                // 0..1
    const int sw     = rowoff & 7;
    uint32_t aRowB[2], bRowB[2];
#pragma unroll
    for (int mt = 0; mt < 2; mt++) aRowB[mt] = (wm * 32 + mt * 16 + rowoff) * 128;
#pragma unroll
    for (int pr = 0; pr < 2; pr++) bRowB[pr] = (wn * 32 + pr * 16 + rowoff) * 128;

    // ping-pong fragments
    uint32_t ah[2][2][4], al[2][2][4], bh[2][4][2], bl[2][4][2];
    float cacc[2][4][4];
#pragma unroll
    for (int i = 0; i < 2; i++)
#pragma unroll
        for (int j = 0; j < 4; j++)
#pragma unroll
            for (int q = 0; q < 4; q++) cacc[i][j][q] = 0.0f;

    auto ldsm_slice = [&](uint32_t stb, int s, int buf) {
        const uint32_t ck = (uint32_t)((((s << 1) + csel) ^ sw) << 4);
#pragma unroll
        for (int mt = 0; mt < 2; mt++) {
            LDSM4(ah[buf][mt], stb + aRowB[mt] + ck);
            LDSM4(al[buf][mt], stb + 16384 + aRowB[mt] + ck);
        }
#pragma unroll
        for (int pr = 0; pr < 2; pr++) {
            uint32_t t[4];
            LDSM4(t, stb + 32768 + bRowB[pr] + ck);
            bh[buf][2 * pr][0] = t[0]; bh[buf][2 * pr + 1][0] = t[1];
            bh[buf][2 * pr][1] = t[2]; bh[buf][2 * pr + 1][1] = t[3];
            LDSM4(t, stb + 49152 + bRowB[pr] + ck);
            bl[buf][2 * pr][0] = t[0]; bl[buf][2 * pr + 1][0] = t[1];
            bl[buf][2 * pr][1] = t[2]; bl[buf][2 * pr + 1][1] = t[3];
        }
    };

    auto mma_all = [&](int buf) {
#pragma unroll
        for (int mt = 0; mt < 2; mt++)
#pragma unroll
            for (int nt = 0; nt < 4; nt++) MMA(cacc[mt][nt], ah[buf][mt], bh[buf][nt]);
#pragma unroll
        for (int mt = 0; mt < 2; mt++)
#pragma unroll
            for (int nt = 0; nt < 4; nt++) MMA(cacc[mt][nt], ah[buf][mt], bl[buf][nt]);
#pragma unroll
        for (int mt = 0; mt < 2; mt++)
#pragma unroll
            for (int nt = 0; nt < 4; nt++) MMA(cacc[mt][nt], al[buf][mt], bh[buf][nt]);
    };

    const int NSt = K >> 6;
    load_stage(0, 0);  CP_COMMIT();
    load_stage(64, 1); CP_COMMIT();
    CP_WAIT1();
    __syncthreads();
    ldsm_slice(sb, 0, 0);

    for (int c = 0; c < NSt; c++) {
        const uint32_t stb = sb + (c % 3) * STAGE_SZ;
#pragma unroll
        for (int s = 0; s < 4; s++) {
            if (s < 3) ldsm_slice(stb, s + 1, (s + 1) & 1);
            mma_all(s & 1);
        }
        if (c + 2 < NSt) load_stage((c + 2) << 6, (c + 2) % 3);
        CP_COMMIT();
        if (c + 1 < NSt) {
            CP_WAIT1();
            __syncthreads();
            ldsm_slice(sb + ((c + 1) % 3) * STAGE_SZ, 0, 0);
        }
    }

    // ---- epilogue ----
    const int l4 = lane >> 2;
    const int l2 = (lane & 3) * 2;
#pragma unroll
    for (int mt = 0; mt < 2; mt++) {
        const int mg = blockIdx.y * 128 + wm * 32 + mt * 16 + l4;
#pragma unroll
        for (int nt = 0; nt < 4; nt++) {
            const int n = blockIdx.x * 128 + wn * 32 + nt * 8 + l2;
            float b0 = 0.f, b1 = 0.f;
            if (HAS_BIAS) { b0 = bias[n]; b1 = bias[n + 1]; }
            float f0 = cacc[mt][nt][0] * alpha + b0;
            float f1 = cacc[mt][nt][1] * alpha + b1;
            float f2 = cacc[mt][nt][2] * alpha + b0;
            float f3 = cacc[mt][nt][3] * alpha + b1;
            if (EPI == 0) {
                float* cb = Cf + blockIdx.z * sC;
                *(float2*)&cb[(long long)mg * N + n]       = make_float2(f0, f1);
                *(float2*)&cb[(long long)(mg + 8) * N + n] = make_float2(f2, f3);
            } else if (EPI == 1) {
                uint32_t h, l;
                split2(f0, f1, h, l);
                *(uint32_t*)&Chi[blockIdx.z * sC + (long long)mg * N + n] = h;
                *(uint32_t*)&Clo[blockIdx.z * sC + (long long)mg * N + n] = l;
                split2(f2, f3, h, l);
                *(uint32_t*)&Chi[blockIdx.z * sC + (long long)(mg + 8) * N + n] = h;
                *(uint32_t*)&Clo[blockIdx.z * sC + (long long)(mg + 8) * N + n] = l;
            } else {
                const int b  = mg >> 11;
                const int s2 = mg & 2047;
                bf16* vh = Chi + (long long)b * EMBED * SEQ + s2;
                bf16* vl = Clo + (long long)b * EMBED * SEQ + s2;
                uint32_t h, l;
                split2(f0, f1, h, l);
                vh[(long long)n * SEQ]       = __ushort_as_bfloat16((unsigned short)(h & 0xFFFF));
                vh[(long long)(n + 1) * SEQ] = __ushort_as_bfloat16((unsigned short)(h >> 16));
                vl[(long long)n * SEQ]       = __ushort_as_bfloat16((unsigned short)(l & 0xFFFF));
                vl[(long long)(n + 1) * SEQ] = __ushort_as_bfloat16((unsigned short)(l >> 16));
                split2(f2, f3, h, l);
                vh[(long long)n * SEQ + 8]       = __ushort_as_bfloat16((unsigned short)(h & 0xFFFF));
                vh[(long long)(n + 1) * SEQ + 8] = __ushort_as_bfloat16((unsigned short)(h >> 16));
                vl[(long long)n * SEQ + 8]       = __ushort_as_bfloat16((unsigned short)(l & 0xFFFF));
                vl[(long long)(n + 1) * SEQ + 8] = __ushort_as_bfloat16((unsigned short)(l >> 16));
            }
        }
    }
}

// ---------------------------------------------------------------------------
__global__ __launch_bounds__(256)
void softmax_kernel(const float* __restrict__ S, bf16* __restrict__ Phi, bf16* __restrict__ Plo)
{
    const float* row = S + (long long)blockIdx.x * SEQ;
    const int t = threadIdx.x;
    const int lane = t & 31;
    const int wid  = t >> 5;

    float4 v0 = ((const float4*)row)[t];
    float4 v1 = ((const float4*)row)[t + 256];

    float m = fmaxf(fmaxf(fmaxf(v0.x, v0.y), fmaxf(v0.z, v0.w)),
                    fmaxf(fmaxf(v1.x, v1.y), fmaxf(v1.z, v1.w)));
#pragma unroll
    for (int o = 16; o > 0; o >>= 1)
        m = fmaxf(m, __shfl_xor_sync(0xFFFFFFFFu, m, o));

    __shared__ float red[8];
    if (lane == 0) red[wid] = m;
    __syncthreads();
    float M = red[0];
#pragma unroll
    for (int i = 1; i < 8; i++) M = fmaxf(M, red[i]);
    __syncthreads();

    v0.x = __expf(v0.x - M); v0.y = __expf(v0.y - M);
    v0.z = __expf(v0.z - M); v0.w = __expf(v0.w - M);
    v1.x = __expf(v1.x - M); v1.y = __expf(v1.y - M);
    v1.z = __expf(v1.z - M); v1.w = __expf(v1.w - M);

    float s = (v0.x + v0.y + v0.z + v0.w) + (v1.x + v1.y + v1.z + v1.w);
#pragma unroll
    for (int o = 16; o > 0; o >>= 1)
        s += __shfl_xor_sync(0xFFFFFFFFu, s, o);
    if (lane == 0) red[wid] = s;
    __syncthreads();
    float Ssum = 0.0f;
#pragma unroll
    for (int i = 0; i < 8; i++) Ssum += red[i];

    const float inv = 1.0f / Ssum;
    v0.x *= inv; v0.y *= inv; v0.z *= inv; v0.w *= inv;
    v1.x *= inv; v1.y *= inv; v1.z *= inv; v1.w *= inv;

    uint2* ph = (uint2*)(Phi + (long long)blockIdx.x * SEQ);
    uint2* pl = (uint2*)(Plo + (long long)blockIdx.x * SEQ);
    uint32_t h01, l01, h23, l23;
    split2(v0.x, v0.y, h01, l01); split2(v0.z, v0.w, h23, l23);
    ph[t] = make_uint2(h01, h23); pl[t] = make_uint2(l01, l23);
    split2(v1.x, v1.y, h01, l01); split2(v1.z, v1.w, h23, l23);
    ph[t + 256] = make_uint2(h01, h23); pl[t + 256] = make_uint2(l01, l23);
}

__global__ __launch_bounds__(256)
void cvt_kernel(const float* __restrict__ src, bf16* __restrict__ hi, bf16* __restrict__ lo, int n4)
{
    int i = blockIdx.x * blockDim.x + threadIdx.x;
    if (i >= n4) return;
    float4 v = ((const float4*)src)[i];
    uint32_t h01, l01, h23, l23;
    split2(v.x, v.y, h01, l01);
    split2(v.z, v.w, h23, l23);
    ((uint2*)hi)[i] = make_uint2(h01, h23);
    ((uint2*)lo)[i] = make_uint2(l01, l23);
}

extern "C" void kernel_launch(void* const* d_in, const int* in_sizes, int n_in,
                              void* d_out, int out_size)
{
    const float* target = (const float*)d_in[0];
    const float* source = (const float*)d_in[1];
    const float* Wq     = (const float*)d_in[2];
    const float* bq     = (const float*)d_in[3];
    const float* Wk     = (const float*)d_in[4];
    const float* bk     = (const float*)d_in[5];
    const float* Wv     = (const float*)d_in[6];
    const float* bv     = (const float*)d_in[7];
    const float* Wo     = (const float*)d_in[8];
    const float* bo     = (const float*)d_in[9];
    float* out = (float*)d_out;

    float* Sc;
    cudaGetSymbolAddress((void**)&Sc, g_Sc);
    bf16 *Thi,*Tlo,*Shi,*Slo,*Wqh,*Wql,*Wkh,*Wkl,*Wvh,*Wvl,*Woh,*Wol;
    bf16 *Qhi,*Qlo,*Khi,*Klo,*Vth,*Vtl,*Phi,*Plo,*Chi,*Clo;
    cudaGetSymbolAddress((void**)&Thi, g_Thi);  cudaGetSymbolAddress((void**)&Tlo, g_Tlo);
    cudaGetSymbolAddress((void**)&Shi, g_Shi);  cudaGetSymbolAddress((void**)&Slo, g_Slo);
    cudaGetSymbolAddress((void**)&Wqh, g_Wqhi); cudaGetSymbolAddress((void**)&Wql, g_Wqlo);
    cudaGetSymbolAddress((void**)&Wkh, g_Wkhi); cudaGetSymbolAddress((void**)&Wkl, g_Wklo);
    cudaGetSymbolAddress((void**)&Wvh, g_Wvhi); cudaGetSymbolAddress((void**)&Wvl, g_Wvlo);
    cudaGetSymbolAddress((void**)&Woh, g_Wohi); cudaGetSymbolAddress((void**)&Wol, g_Wolo);
    cudaGetSymbolAddress((void**)&Qhi, g_Qhi);  cudaGetSymbolAddress((void**)&Qlo, g_Qlo);
    cudaGetSymbolAddress((void**)&Khi, g_Khi);  cudaGetSymbolAddress((void**)&Klo, g_Klo);
    cudaGetSymbolAddress((void**)&Vth, g_Vthi); cudaGetSymbolAddress((void**)&Vtl, g_Vtlo);
    cudaGetSymbolAddress((void**)&Phi, g_Phi);  cudaGetSymbolAddress((void**)&Plo, g_Plo);
    cudaGetSymbolAddress((void**)&Chi, g_Chi);  cudaGetSymbolAddress((void**)&Clo, g_Clo);

    cudaFuncSetAttribute(mm_kernel<1, 1>, cudaFuncAttributeMaxDynamicSharedMemorySize, SMEM_BYTES);
    cudaFuncSetAttribute(mm_kernel<1, 2>, cudaFuncAttributeMaxDynamicSharedMemorySize, SMEM_BYTES);
    cudaFuncSetAttribute(mm_kernel<0, 0>, cudaFuncAttributeMaxDynamicSharedMemorySize, SMEM_BYTES);
    cudaFuncSetAttribute(mm_kernel<0, 1>, cudaFuncAttributeMaxDynamicSharedMemorySize, SMEM_BYTES);
    cudaFuncSetAttribute(mm_kernel<1, 0>, cudaFuncAttributeMaxDynamicSharedMemorySize, SMEM_BYTES);

    const int nIn  = MTOT * EMBED / 4;
    const int nW   = EMBED * EMBED / 4;
    // launches 0-4 (ncu -s 5 -c 1 captures launch idx 5 = first proj GEMM)
    cvt_kernel<<<(nIn + 255) / 256, 256>>>(target, Thi, Tlo, nIn);
    cvt_kernel<<<(nIn + 255) / 256, 256>>>(source, Shi, Slo, nIn);
    cvt_kernel<<<(nW + 255) / 256, 256>>>(Wq, Wqh, Wql, nW);
    cvt_kernel<<<(nW + 255) / 256, 256>>>(Wk, Wkh, Wkl, nW);
    cvt_kernel<<<(nW + 255) / 256, 256>>>(Wv, Wvh, Wvl, nW);

    dim3 gProj(EMBED / 128, MTOT / 128, 1);
    mm_kernel<1, 1><<<gProj, 512, SMEM_BYTES>>>(Thi, Tlo, Wqh, Wql, bq, nullptr, Qhi, Qlo,
                                                MTOT, EMBED, EMBED, 0, 0, 0, 1.0f);
    mm_kernel<1, 1><<<gProj, 512, SMEM_BYTES>>>(Shi, Slo, Wkh, Wkl, bk, nullptr, Khi, Klo,
                                                MTOT, EMBED, EMBED, 0, 0, 0, 1.0f);
    mm_kernel<1, 2><<<gProj, 512, SMEM_BYTES>>>(Shi, Slo, Wvh, Wvl, bv, nullptr, Vth, Vtl,
                                                MTOT, EMBED, EMBED, 0, 0, 0, 1.0f);

    dim3 gScore(SEQ / 128, SEQ / 128, BATCH);
    mm_kernel<0, 0><<<gScore, 512, SMEM_BYTES>>>(Qhi, Qlo, Khi, Klo, nullptr, Sc, nullptr, nullptr,
                                                 SEQ, SEQ, EMBED,
                                                 (long long)SEQ * EMBED, (long long)SEQ * EMBED,
                                                 (long long)SEQ * SEQ, 0.03125f);

    softmax_kernel<<<BATCH * SEQ, 256>>>(Sc, Phi, Plo);

    dim3 gAV(EMBED / 128, SEQ / 128, BATCH);
    mm_kernel<0, 1><<<gAV, 512, SMEM_BYTES>>>(Phi, Plo, Vth, Vtl, nullptr, nullptr, Chi, Clo,
                                              SEQ, EMBED, SEQ,
                                              (long long)SEQ * SEQ, (long long)EMBED * SEQ,
                                              (long long)SEQ * EMBED, 1.0f);

    cvt_kernel<<<(nW + 255) / 256, 256>>>(Wo, Woh, Wol, nW);
    mm_kernel<1, 0><<<gProj, 512, SMEM_BYTES>>>(Chi, Clo, Woh, Wol, bo, out, nullptr, nullptr,
                                                MTOT, EMBED, EMBED, 0, 0, 0, 1.0f);
}

// round 10
// speedup vs baseline: 3.7015x; 1.4346x over previous
#include <cuda_runtime.h>
#include <cuda_fp16.h>
#include <cstdint>
#include <math.h>

// ---------------------------------------------------------------------------
// CrossAttention B=8, T=S=2048, D=1024 (single head).
// R8: fp16 2-product split (A = Ah+Al full, B = Bh truncated) on mma.sync
// m16n8k16.f16. 128x128 CTA tile, 512 threads, warp tile 32x32, K64 stages x3,
// fragment ping-pong. MMA work = 2/3 of the bf16 3-product scheme.
// ---------------------------------------------------------------------------

#define EMBED 1024
#define BATCH 8
#define SEQ   2048
#define MTOT  (BATCH * SEQ)

typedef __half h16;

__device__ float g_Sc[(long long)BATCH * SEQ * SEQ];
__device__ h16 g_Thi[MTOT * EMBED], g_Tlo[MTOT * EMBED];
__device__ h16 g_Shi[MTOT * EMBED], g_Slo[MTOT * EMBED];
__device__ h16 g_Wqhi[EMBED * EMBED];
__device__ h16 g_Wkhi[EMBED * EMBED];
__device__ h16 g_Wvhi[EMBED * EMBED];
__device__ h16 g_Wohi[EMBED * EMBED];
__device__ h16 g_Qhi[MTOT * EMBED],  g_Qlo[MTOT * EMBED];
__device__ h16 g_Khi[MTOT * EMBED];                         // B operand: hi only
__device__ h16 g_Vthi[MTOT * EMBED];                        // [B][D][S], hi only
__device__ h16 g_Phi[(long long)BATCH * SEQ * SEQ], g_Plo[(long long)BATCH * SEQ * SEQ];
__device__ h16 g_Chi[MTOT * EMBED],  g_Clo[MTOT * EMBED];

__device__ __forceinline__ uint32_t smem_u32(const void* p) {
    uint32_t a;
    asm("{ .reg .u64 t; cvta.to.shared.u64 t, %1; cvt.u32.u64 %0, t; }" : "=r"(a) : "l"(p));
    return a;
}

#define LDSM4(r, addr) \
    asm volatile("ldmatrix.sync.aligned.m8n8.x4.shared.b16 {%0,%1,%2,%3}, [%4];" \
        : "=r"((r)[0]), "=r"((r)[1]), "=r"((r)[2]), "=r"((r)[3]) : "r"(addr))

#define MMA(d, a, b) \
    asm volatile("mma.sync.aligned.m16n8k16.row.col.f32.f16.f16.f32 " \
        "{%0,%1,%2,%3}, {%4,%5,%6,%7}, {%8,%9}, {%0,%1,%2,%3};" \
        : "+f"((d)[0]), "+f"((d)[1]), "+f"((d)[2]), "+f"((d)[3]) \
        : "r"((a)[0]), "r"((a)[1]), "r"((a)[2]), "r"((a)[3]), "r"((b)[0]), "r"((b)[1]))

#define CP16(dst, src) \
    asm volatile("cp.async.cg.shared.global [%0], [%1], 16;" :: "r"(dst), "l"(src))
#define CP_COMMIT() asm volatile("cp.async.commit_group;" ::: "memory")
#define CP_WAIT1()  asm volatile("cp.async.wait_group 1;" ::: "memory")

// two fp32 -> packed fp16 hi pair + packed fp16 residual pair (f0 low, f1 high)
__device__ __forceinline__ void split2h(float f0, float f1, uint32_t& hi, uint32_t& lo) {
    asm("cvt.rn.f16x2.f32 %0, %1, %2;" : "=r"(hi) : "f"(f1), "f"(f0));
    float h0, h1;
    asm("{ .reg .b16 l, h; mov.b32 {l, h}, %2; cvt.f32.f16 %0, l; cvt.f32.f16 %1, h; }"
        : "=f"(h0), "=f"(h1) : "r"(hi));
    float r0 = f0 - h0, r1 = f1 - h1;
    asm("cvt.rn.f16x2.f32 %0, %1, %2;" : "=r"(lo) : "f"(r1), "f"(r0));
}
// two fp32 -> packed fp16 (hi only)
__device__ __forceinline__ uint32_t cvt2h(float f0, float f1) {
    uint32_t h;
    asm("cvt.rn.f16x2.f32 %0, %1, %2;" : "=r"(h) : "f"(f1), "f"(f0));
    return h;
}

// Stage (48 KB): Ahi[0,16K) Alo[16K,32K) Bhi[32K,48K)
// 128 rows x 128B (64 fp16, K64). 8 chunks of 16B/row; swizzle chunk ^= row&7.
#define STAGE_SZ 49152
#define STAGES   3
#define SMEM_BYTES (STAGES * STAGE_SZ)

// C = alpha * (Ahi+Alo) @ Bhi^T (+bias).
// EPI: 0=fp32, 1=hi/lo fp16, 2=hi-only fp16, 3=hi-only fp16 transposed [B][D][S]
template <int HAS_BIAS, int EPI>
__global__ __launch_bounds__(512, 1)
void mm_kernel(const h16* __restrict__ Ahi, const h16* __restrict__ Alo,
               const h16* __restrict__ Bhi,
               const float* __restrict__ bias,
               float* __restrict__ Cf, h16* __restrict__ Chi, h16* __restrict__ Clo,
               int M, int N, int K,
               long long sA, long long sB, long long sC, float alpha)
{
    extern __shared__ char sm[];
    const uint32_t sb = smem_u32(sm);
    const int tid  = threadIdx.x;
    const int lane = tid & 31;
    const int wid  = tid >> 5;
    const int wm   = wid >> 2;   // 0..3 (32 rows)
    const int wn   = wid & 3;    // 0..3 (32 cols)

    const long long aoff = blockIdx.z * sA + (long long)(blockIdx.y * 128) * K;
    const long long boff = blockIdx.z * sB + (long long)(blockIdx.x * 128) * K;

    // ---- loader: 512 thr x 1.5 rows-worth: 3 tiles x 128 rows x 8 chunks = 3072 chunks,
    // 6 per thread. Map: tid -> row = tid>>2, chunks {cg, cg+1} per tile.
    const int lrow = tid >> 2;
    const int cg   = (tid & 3) * 2;
    const int swr  = lrow & 7;
    const uint32_t d0 = lrow * 128 + ((cg ^ swr) << 4);
    const uint32_t d1 = lrow * 128 + (((cg + 1) ^ swr) << 4);
    const h16* pAhi = Ahi + aoff + (long long)lrow * K + cg * 8;
    const h16* pAlo = Alo + aoff + (long long)lrow * K + cg * 8;
    const h16* pBhi = Bhi + boff + (long long)lrow * K + cg * 8;

    auto load_stage = [&](int kofs, int st) {
        const uint32_t stb = sb + st * STAGE_SZ;
        CP16(stb + d0,         pAhi + kofs);
        CP16(stb + d1,         pAhi + kofs + 8);
        CP16(stb + 16384 + d0, pAlo + kofs);
        CP16(stb + 16384 + d1, pAlo + kofs + 8);
        CP16(stb + 32768 + d0, pBhi + kofs);
        CP16(stb + 32768 + d1, pBhi + kofs + 8);
    };

    // ---- ldmatrix addressing ----
    const int g      = lane >> 3;
    const int rr     = lane & 7;
    const int rowoff = ((g & 1) << 3) + rr;   // 0..15
    const int csel   = g >> 1;                // 0..1
    const int sw     = rowoff & 7;
    uint32_t aRowB[2], bRowB[2];
#pragma unroll
    for (int mt = 0; mt < 2; mt++) aRowB[mt] = (wm * 32 + mt * 16 + rowoff) * 128;
#pragma unroll
    for (int pr = 0; pr < 2; pr++) bRowB[pr] = (wn * 32 + pr * 16 + rowoff) * 128;

    // ping-pong fragments
    uint32_t ah[2][2][4], al[2][2][4], bh[2][4][2];
    float cacc[2][4][4];
#pragma unroll
    for (int i = 0; i < 2; i++)
#pragma unroll
        for (int j = 0; j < 4; j++)
#pragma unroll
            for (int q = 0; q < 4; q++) cacc[i][j][q] = 0.0f;

    auto ldsm_slice = [&](uint32_t stb, int s, int buf) {
        const uint32_t ck = (uint32_t)((((s << 1) + csel) ^ sw) << 4);
#pragma unroll
        for (int mt = 0; mt < 2; mt++) {
            LDSM4(ah[buf][mt], stb + aRowB[mt] + ck);
            LDSM4(al[buf][mt], stb + 16384 + aRowB[mt] + ck);
        }
#pragma unroll
        for (int pr = 0; pr < 2; pr++) {
            uint32_t t[4];
            LDSM4(t, stb + 32768 + bRowB[pr] + ck);
            bh[buf][2 * pr][0] = t[0]; bh[buf][2 * pr + 1][0] = t[1];
            bh[buf][2 * pr][1] = t[2]; bh[buf][2 * pr + 1][1] = t[3];
        }
    };

    auto mma_all = [&](int buf) {
#pragma unroll
        for (int mt = 0; mt < 2; mt++)
#pragma unroll
            for (int nt = 0; nt < 4; nt++) MMA(cacc[mt][nt], ah[buf][mt], bh[buf][nt]);
#pragma unroll
        for (int mt = 0; mt < 2; mt++)
#pragma unroll
            for (int nt = 0; nt < 4; nt++) MMA(cacc[mt][nt], al[buf][mt], bh[buf][nt]);
    };

    const int NSt = K >> 6;
    load_stage(0, 0);  CP_COMMIT();
    load_stage(64, 1); CP_COMMIT();
    CP_WAIT1();
    __syncthreads();
    ldsm_slice(sb, 0, 0);

    for (int c = 0; c < NSt; c++) {
        const uint32_t stb = sb + (c % 3) * STAGE_SZ;
#pragma unroll
        for (int s = 0; s < 4; s++) {
            if (s < 3) ldsm_slice(stb, s + 1, (s + 1) & 1);
            mma_all(s & 1);
        }
        if (c + 2 < NSt) load_stage((c + 2) << 6, (c + 2) % 3);
        CP_COMMIT();
        if (c + 1 < NSt) {
            CP_WAIT1();
            __syncthreads();
            ldsm_slice(sb + ((c + 1) % 3) * STAGE_SZ, 0, 0);
        }
    }

    // ---- epilogue ----
    const int l4 = lane >> 2;
    const int l2 = (lane & 3) * 2;
#pragma unroll
    for (int mt = 0; mt < 2; mt++) {
        const int mg = blockIdx.y * 128 + wm * 32 + mt * 16 + l4;
#pragma unroll
        for (int nt = 0; nt < 4; nt++) {
            const int n = blockIdx.x * 128 + wn * 32 + nt * 8 + l2;
            float b0 = 0.f, b1 = 0.f;
            if (HAS_BIAS) { b0 = bias[n]; b1 = bias[n + 1]; }
            float f0 = cacc[mt][nt][0] * alpha + b0;
            float f1 = cacc[mt][nt][1] * alpha + b1;
            float f2 = cacc[mt][nt][2] * alpha + b0;
            float f3 = cacc[mt][nt][3] * alpha + b1;
            if (EPI == 0) {
                float* cb = Cf + blockIdx.z * sC;
                *(float2*)&cb[(long long)mg * N + n]       = make_float2(f0, f1);
                *(float2*)&cb[(long long)(mg + 8) * N + n] = make_float2(f2, f3);
            } else if (EPI == 1) {
                uint32_t h, l;
                split2h(f0, f1, h, l);
                *(uint32_t*)&Chi[blockIdx.z * sC + (long long)mg * N + n] = h;
                *(uint32_t*)&Clo[blockIdx.z * sC + (long long)mg * N + n] = l;
                split2h(f2, f3, h, l);
                *(uint32_t*)&Chi[blockIdx.z * sC + (long long)(mg + 8) * N + n] = h;
                *(uint32_t*)&Clo[blockIdx.z * sC + (long long)(mg + 8) * N + n] = l;
            } else if (EPI == 2) {
                *(uint32_t*)&Chi[blockIdx.z * sC + (long long)mg * N + n]       = cvt2h(f0, f1);
                *(uint32_t*)&Chi[blockIdx.z * sC + (long long)(mg + 8) * N + n] = cvt2h(f2, f3);
            } else {
                // hi-only transposed: row m -> (b, s), col n -> Vt[b][n][s]
                const int b  = mg >> 11;
                const int s2 = mg & 2047;
                uint16_t* vh = (uint16_t*)(Chi + (long long)b * EMBED * SEQ + s2);
                uint32_t h = cvt2h(f0, f1);
                vh[(long long)n * SEQ]       = (uint16_t)(h & 0xFFFF);
                vh[(long long)(n + 1) * SEQ] = (uint16_t)(h >> 16);
                h = cvt2h(f2, f3);
                vh[(long long)n * SEQ + 8]       = (uint16_t)(h & 0xFFFF);
                vh[(long long)(n + 1) * SEQ + 8] = (uint16_t)(h >> 16);
            }
        }
    }
}

// ---------------------------------------------------------------------------
__global__ __launch_bounds__(256)
void softmax_kernel(const float* __restrict__ S, h16* __restrict__ Phi, h16* __restrict__ Plo)
{
    const float* row = S + (long long)blockIdx.x * SEQ;
    const int t = threadIdx.x;
    const int lane = t & 31;
    const int wid  = t >> 5;

    float4 v0 = ((const float4*)row)[t];
    float4 v1 = ((const float4*)row)[t + 256];

    float m = fmaxf(fmaxf(fmaxf(v0.x, v0.y), fmaxf(v0.z, v0.w)),
                    fmaxf(fmaxf(v1.x, v1.y), fmaxf(v1.z, v1.w)));
#pragma unroll
    for (int o = 16; o > 0; o >>= 1)
        m = fmaxf(m, __shfl_xor_sync(0xFFFFFFFFu, m, o));

    __shared__ float red[8];
    if (lane == 0) red[wid] = m;
    __syncthreads();
    float M = red[0];
#pragma unroll
    for (int i = 1; i < 8; i++) M = fmaxf(M, red[i]);
    __syncthreads();

    v0.x = __expf(v0.x - M); v0.y = __expf(v0.y - M);
    v0.z = __expf(v0.z - M); v0.w = __expf(v0.w - M);
    v1.x = __expf(v1.x - M); v1.y = __expf(v1.y - M);
    v1.z = __expf(v1.z - M); v1.w = __expf(v1.w - M);

    float s = (v0.x + v0.y + v0.z + v0.w) + (v1.x + v1.y + v1.z + v1.w);
#pragma unroll
    for (int o = 16; o > 0; o >>= 1)
        s += __shfl_xor_sync(0xFFFFFFFFu, s, o);
    if (lane == 0) red[wid] = s;
    __syncthreads();
    float Ssum = 0.0f;
#pragma unroll
    for (int i = 0; i < 8; i++) Ssum += red[i];

    const float inv = 1.0f / Ssum;
    v0.x *= inv; v0.y *= inv; v0.z *= inv; v0.w *= inv;
    v1.x *= inv; v1.y *= inv; v1.z *= inv; v1.w *= inv;

    uint2* ph = (uint2*)(Phi + (long long)blockIdx.x * SEQ);
    uint2* pl = (uint2*)(Plo + (long long)blockIdx.x * SEQ);
    uint32_t h01, l01, h23, l23;
    split2h(v0.x, v0.y, h01, l01); split2h(v0.z, v0.w, h23, l23);
    ph[t] = make_uint2(h01, h23); pl[t] = make_uint2(l01, l23);
    split2h(v1.x, v1.y, h01, l01); split2h(v1.z, v1.w, h23, l23);
    ph[t + 256] = make_uint2(h01, h23); pl[t + 256] = make_uint2(l01, l23);
}

// fp32 -> hi/lo fp16 (A operands)
__global__ __launch_bounds__(256)
void cvt_kernel(const float* __restrict__ src, h16* __restrict__ hi, h16* __restrict__ lo, int n4)
{
    int i = blockIdx.x * blockDim.x + threadIdx.x;
    if (i >= n4) return;
    float4 v = ((const float4*)src)[i];
    uint32_t h01, l01, h23, l23;
    split2h(v.x, v.y, h01, l01);
    split2h(v.z, v.w, h23, l23);
    ((uint2*)hi)[i] = make_uint2(h01, h23);
    ((uint2*)lo)[i] = make_uint2(l01, l23);
}

// fp32 -> hi fp16 only (B operands / weights)
__global__ __launch_bounds__(256)
void cvth_kernel(const float* __restrict__ src, h16* __restrict__ hi, int n4)
{
    int i = blockIdx.x * blockDim.x + threadIdx.x;
    if (i >= n4) return;
    float4 v = ((const float4*)src)[i];
    ((uint2*)hi)[i] = make_uint2(cvt2h(v.x, v.y), cvt2h(v.z, v.w));
}

extern "C" void kernel_launch(void* const* d_in, const int* in_sizes, int n_in,
                              void* d_out, int out_size)
{
    const float* target = (const float*)d_in[0];
    const float* source = (const float*)d_in[1];
    const float* Wq     = (const float*)d_in[2];
    const float* bq     = (const float*)d_in[3];
    const float* Wk     = (const float*)d_in[4];
    const float* bk     = (const float*)d_in[5];
    const float* Wv     = (const float*)d_in[6];
    const float* bv     = (const float*)d_in[7];
    const float* Wo     = (const float*)d_in[8];
    const float* bo     = (const float*)d_in[9];
    float* out = (float*)d_out;

    float* Sc;
    cudaGetSymbolAddress((void**)&Sc, g_Sc);
    h16 *Thi,*Tlo,*Shi,*Slo,*Wqh,*Wkh,*Wvh,*Woh;
    h16 *Qhi,*Qlo,*Khi,*Vth,*Phi,*Plo,*Chi,*Clo;
    cudaGetSymbolAddress((void**)&Thi, g_Thi);  cudaGetSymbolAddress((void**)&Tlo, g_Tlo);
    cudaGetSymbolAddress((void**)&Shi, g_Shi);  cudaGetSymbolAddress((void**)&Slo, g_Slo);
    cudaGetSymbolAddress((void**)&Wqh, g_Wqhi);
    cudaGetSymbolAddress((void**)&Wkh, g_Wkhi);
    cudaGetSymbolAddress((void**)&Wvh, g_Wvhi);
    cudaGetSymbolAddress((void**)&Woh, g_Wohi);
    cudaGetSymbolAddress((void**)&Qhi, g_Qhi);  cudaGetSymbolAddress((void**)&Qlo, g_Qlo);
    cudaGetSymbolAddress((void**)&Khi, g_Khi);
    cudaGetSymbolAddress((void**)&Vth, g_Vthi);
    cudaGetSymbolAddress((void**)&Phi, g_Phi);  cudaGetSymbolAddress((void**)&Plo, g_Plo);
    cudaGetSymbolAddress((void**)&Chi, g_Chi);  cudaGetSymbolAddress((void**)&Clo, g_Clo);

    cudaFuncSetAttribute(mm_kernel<1, 1>, cudaFuncAttributeMaxDynamicSharedMemorySize, SMEM_BYTES);
    cudaFuncSetAttribute(mm_kernel<1, 2>, cudaFuncAttributeMaxDynamicSharedMemorySize, SMEM_BYTES);
    cudaFuncSetAttribute(mm_kernel<1, 3>, cudaFuncAttributeMaxDynamicSharedMemorySize, SMEM_BYTES);
    cudaFuncSetAttribute(mm_kernel<0, 0>, cudaFuncAttributeMaxDynamicSharedMemorySize, SMEM_BYTES);
    cudaFuncSetAttribute(mm_kernel<0, 1>, cudaFuncAttributeMaxDynamicSharedMemorySize, SMEM_BYTES);
    cudaFuncSetAttribute(mm_kernel<1, 0>, cudaFuncAttributeMaxDynamicSharedMemorySize, SMEM_BYTES);

    const int nIn  = MTOT * EMBED / 4;
    const int nW   = EMBED * EMBED / 4;
    // launches 0-4 (ncu -s 5 -c 1 captures idx 5 = Q projection GEMM)
    cvt_kernel<<<(nIn + 255) / 256, 256>>>(target, Thi, Tlo, nIn);
    cvt_kernel<<<(nIn + 255) / 256, 256>>>(source, Shi, Slo, nIn);
    cvth_kernel<<<(nW + 255) / 256, 256>>>(Wq, Wqh, nW);
    cvth_kernel<<<(nW + 255) / 256, 256>>>(Wk, Wkh, nW);
    cvth_kernel<<<(nW + 255) / 256, 256>>>(Wv, Wvh, nW);

    dim3 gProj(EMBED / 128, MTOT / 128, 1);
    // Q: needs hi+lo (A operand of score GEMM)
    mm_kernel<1, 1><<<gProj, 512, SMEM_BYTES>>>(Thi, Tlo, Wqh, bq, nullptr, Qhi, Qlo,
                                                MTOT, EMBED, EMBED, 0, 0, 0, 1.0f);
    // K: hi only (B operand)
    mm_kernel<1, 2><<<gProj, 512, SMEM_BYTES>>>(Shi, Slo, Wkh, bk, nullptr, Khi, nullptr,
                                                MTOT, EMBED, EMBED, 0, 0, 0, 1.0f);
    // V: hi only, transposed -> [B][D][S]
    mm_kernel<1, 3><<<gProj, 512, SMEM_BYTES>>>(Shi, Slo, Wvh, bv, nullptr, Vth, nullptr,
                                                MTOT, EMBED, EMBED, 0, 0, 0, 1.0f);

    dim3 gScore(SEQ / 128, SEQ / 128, BATCH);
    mm_kernel<0, 0><<<gScore, 512, SMEM_BYTES>>>(Qhi, Qlo, Khi, nullptr, Sc, nullptr, nullptr,
                                                 SEQ, SEQ, EMBED,
                                                 (long long)SEQ * EMBED, (long long)SEQ * EMBED,
                                                 (long long)SEQ * SEQ, 0.03125f);

    softmax_kernel<<<BATCH * SEQ, 256>>>(Sc, Phi, Plo);

    dim3 gAV(EMBED / 128, SEQ / 128, BATCH);
    // ctx: hi+lo (A operand of final proj)
    mm_kernel<0, 1><<<gAV, 512, SMEM_BYTES>>>(Phi, Plo, Vth, nullptr, nullptr, Chi, Clo,
                                              SEQ, EMBED, SEQ,
                                              (long long)SEQ * SEQ, (long long)EMBED * SEQ,
                                              (long long)SEQ * EMBED, 1.0f);

    cvth_kernel<<<(nW + 255) / 256, 256>>>(Wo, Woh, nW);
    mm_kernel<1, 0><<<gProj, 512, SMEM_BYTES>>>(Chi, Clo, Woh, bo, out, nullptr, nullptr,
                                                MTOT, EMBED, EMBED, 0, 0, 0, 1.0f);
}